// round 1
// baseline (speedup 1.0000x reference)
#include <cuda_runtime.h>
#include <math.h>

#define QLEN 512
#define MLEN 512
#define KLEN 1024
#define BSZ  16
#define NH   16
#define DH   64
#define DM   1024
#define HID  1024
#define QKV3 3072

// ---------------- scratch (no cudaMalloc allowed) ----------------
__device__ float g_Q [(size_t)BSZ*NH*QLEN*DH];          // [(b*NH+n)*QLEN + i]*DH + d
__device__ float g_K [(size_t)BSZ*NH*KLEN*DH];          // [(b*NH+n)*KLEN + j]*DH + d
__device__ float g_V [(size_t)BSZ*NH*KLEN*DH];
__device__ float g_Rk[(size_t)NH*KLEN*DH];              // [n*KLEN + u]*DH + d
__device__ float g_BD[(size_t)BSZ*NH*QLEN*KLEN];        // [(b*NH+n)*QLEN + i]*KLEN + u
__device__ float g_AV[(size_t)QLEN*BSZ*HID];            // [(i*BSZ+b)*HID + n*DH + d]

// ---------------- generic 128x128x16 SGEMM, K = 1024 ----------------
// MODE 0: A = cat(mems, w) (16384 rows), B = qkv_w (ldb 3072), scatter Q/K/V
// MODE 1: A = r (1024 rows),             B = r_w  (ldb 1024), scatter Rk
// MODE 2: A = g_AV (8192 rows),          B = o_w  (ldb 1024), plain C
template<int MODE>
__global__ __launch_bounds__(256) void gemm128(
    const float* __restrict__ A0, const float* __restrict__ A1,
    const float* __restrict__ B, float* __restrict__ C, int ldb)
{
    __shared__ float As[16][128];
    __shared__ float Bs[16][128];
    const int tid = threadIdx.x;
    const int m0 = blockIdx.y * 128;
    const int n0 = blockIdx.x * 128;
    const int tm = (tid >> 4) << 3;
    const int tn = (tid & 15) << 3;

    float acc[8][8];
#pragma unroll
    for (int i = 0; i < 8; i++)
#pragma unroll
        for (int j = 0; j < 8; j++) acc[i][j] = 0.f;

    for (int k0 = 0; k0 < 1024; k0 += 16) {
#pragma unroll
        for (int l = 0; l < 2; l++) {
            int idx = tid + l * 256;          // 0..511
            int ar  = idx >> 2;               // 0..127
            int ac  = (idx & 3) << 2;         // 0,4,8,12
            int m   = m0 + ar;
            const float* arow;
            if (MODE == 0)
                arow = (m < 8192) ? (A0 + (size_t)m * 1024)
                                  : (A1 + (size_t)(m - 8192) * 1024);
            else if (MODE == 1)
                arow = A0 + (size_t)m * 1024;
            else
                arow = g_AV + (size_t)m * 1024;
            float4 v = *(const float4*)(arow + k0 + ac);
            As[ac + 0][ar] = v.x; As[ac + 1][ar] = v.y;
            As[ac + 2][ar] = v.z; As[ac + 3][ar] = v.w;
        }
#pragma unroll
        for (int l = 0; l < 2; l++) {
            int idx = tid + l * 256;
            int br  = idx >> 5;               // 0..15
            int bc  = (idx & 31) << 2;        // 0..124
            float4 v = *(const float4*)(B + (size_t)(k0 + br) * ldb + n0 + bc);
            *(float4*)&Bs[br][bc] = v;
        }
        __syncthreads();
#pragma unroll
        for (int kk = 0; kk < 16; kk++) {
            float af[8], bf[8];
#pragma unroll
            for (int i = 0; i < 8; i++) af[i] = As[kk][tm + i];
#pragma unroll
            for (int j = 0; j < 8; j++) bf[j] = Bs[kk][tn + j];
#pragma unroll
            for (int i = 0; i < 8; i++)
#pragma unroll
                for (int j = 0; j < 8; j++)
                    acc[i][j] = fmaf(af[i], bf[j], acc[i][j]);
        }
        __syncthreads();
    }

    if (MODE == 0) {
#pragma unroll
        for (int i = 0; i < 8; i++) {
            int m  = m0 + tm + i;
            int kl = m >> 4, b = m & 15;
#pragma unroll
            for (int j = 0; j < 8; j++) {
                int col = n0 + tn + j;
                int sec = col >> 10;
                int hn  = (col >> 6) & 15;
                int d   = col & 63;
                float v = acc[i][j];
                if (sec == 0) {
                    if (kl >= MLEN)
                        g_Q[((size_t)(b*NH+hn)*QLEN + (kl-MLEN))*DH + d] = v;
                } else if (sec == 1) {
                    g_K[((size_t)(b*NH+hn)*KLEN + kl)*DH + d] = v;
                } else {
                    g_V[((size_t)(b*NH+hn)*KLEN + kl)*DH + d] = v;
                }
            }
        }
    } else if (MODE == 1) {
#pragma unroll
        for (int i = 0; i < 8; i++) {
            int u = m0 + tm + i;
#pragma unroll
            for (int j = 0; j < 8; j++) {
                int col = n0 + tn + j;
                int hn = col >> 6, d = col & 63;
                g_Rk[((size_t)hn*KLEN + u)*DH + d] = acc[i][j];
            }
        }
    } else {
#pragma unroll
        for (int i = 0; i < 8; i++) {
            int m = m0 + tm + i;
            float* crow = C + (size_t)m * 1024 + n0 + tn;
            *(float4*)(crow + 0) = make_float4(acc[i][0], acc[i][1], acc[i][2], acc[i][3]);
            *(float4*)(crow + 4) = make_float4(acc[i][4], acc[i][5], acc[i][6], acc[i][7]);
        }
    }
}

// ---------------- BD GEMM: BD[b,n,i,u] = (q[i]+rr_bias) . rk[u], K = 64 ----------------
__global__ __launch_bounds__(256) void bd_kernel(const float* __restrict__ rrb)
{
    const int i0 = blockIdx.x * 64;
    const int bn = blockIdx.y;            // b*16+n
    const int b = bn >> 4, n = bn & 15;
    __shared__ float Qs[64][65];
    __shared__ float Rs[64][65];
    const int tid = threadIdx.x;
    const int ty = tid >> 4, tx = tid & 15;

    const float* qbase = g_Q + ((size_t)(b*NH+n)*QLEN + i0) * DH;
    for (int t = tid; t < 64*64; t += 256) {
        int r = t >> 6, d = t & 63;
        Qs[r][d] = qbase[r*64 + d] + rrb[n*64 + d];
    }
    float* outbase = g_BD + ((size_t)(b*NH+n)*QLEN + i0) * KLEN;

    for (int u0 = 0; u0 < KLEN; u0 += 64) {
        __syncthreads();
        const float* rkbase = g_Rk + ((size_t)n*KLEN + u0) * DH;
        for (int t = tid; t < 64*64; t += 256) {
            int r = t >> 6, d = t & 63;
            Rs[r][d] = rkbase[r*64 + d];
        }
        __syncthreads();
        float acc[4][4] = {};
#pragma unroll
        for (int d = 0; d < 64; d++) {
            float qf[4], rf[4];
#pragma unroll
            for (int ii = 0; ii < 4; ii++) qf[ii] = Qs[ty*4+ii][d];
#pragma unroll
            for (int uu = 0; uu < 4; uu++) rf[uu] = Rs[tx*4+uu][d];
#pragma unroll
            for (int ii = 0; ii < 4; ii++)
#pragma unroll
                for (int uu = 0; uu < 4; uu++)
                    acc[ii][uu] = fmaf(qf[ii], rf[uu], acc[ii][uu]);
        }
#pragma unroll
        for (int ii = 0; ii < 4; ii++)
#pragma unroll
            for (int uu = 0; uu < 4; uu++)
                outbase[(size_t)(ty*4+ii)*KLEN + u0 + tx*4 + uu] = acc[ii][uu];
    }
}

// ---------------- fused attention with online softmax ----------------
// score(i,j) = ( (q_i + rw_bias) . k_j  +  BD[i, j+511-i] ) * 0.125,  j <= i+MLEN
__global__ __launch_bounds__(256) void attn_kernel(const float* __restrict__ rwb)
{
    const int i0 = blockIdx.x * 64;
    const int bn = blockIdx.y;
    const int b = bn >> 4, n = bn & 15;
    const int tid = threadIdx.x;
    const int ty = tid >> 4, tx = tid & 15;

    __shared__ float Qs [64][65];   // [i][d]  q + rw_bias
    __shared__ float KVt[64][33];   // [d][jl] transposed K, then V
    __shared__ float Ps [64][33];   // [i][jl] probabilities

    const float* qbase = g_Q + ((size_t)(b*NH+n)*QLEN + i0) * DH;
    for (int t = tid; t < 4096; t += 256) {
        int r = t >> 6, d = t & 63;
        Qs[r][d] = qbase[r*64 + d] + rwb[n*64 + d];
    }

    float mi[4], li[4], oacc[4][4];
#pragma unroll
    for (int ii = 0; ii < 4; ii++) {
        mi[ii] = -INFINITY; li[ii] = 0.f;
#pragma unroll
        for (int dd = 0; dd < 4; dd++) oacc[ii][dd] = 0.f;
    }

    const float* kbase  = g_K + (size_t)(b*NH+n)*KLEN*DH;
    const float* vbase  = g_V + (size_t)(b*NH+n)*KLEN*DH;
    const float* bdbase = g_BD + ((size_t)(b*NH+n)*QLEN + i0) * KLEN;
    const int   jmax  = i0 + 576;        // exclusive, multiple of 32, <= 1024
    const float scale = 0.125f;

    for (int j0 = 0; j0 < jmax; j0 += 32) {
        __syncthreads();
        for (int t = tid; t < 2048; t += 256) {
            int jl = t >> 6, d = t & 63;
            KVt[d][jl] = kbase[(size_t)(j0+jl)*64 + d];
        }
        __syncthreads();

        float s[4][2];
#pragma unroll
        for (int ii = 0; ii < 4; ii++) { s[ii][0] = 0.f; s[ii][1] = 0.f; }
#pragma unroll
        for (int d = 0; d < 64; d++) {
            float qf[4];
#pragma unroll
            for (int ii = 0; ii < 4; ii++) qf[ii] = Qs[ty*4+ii][d];
            float k0f = KVt[d][tx*2+0];
            float k1f = KVt[d][tx*2+1];
#pragma unroll
            for (int ii = 0; ii < 4; ii++) {
                s[ii][0] = fmaf(qf[ii], k0f, s[ii][0]);
                s[ii][1] = fmaf(qf[ii], k1f, s[ii][1]);
            }
        }
#pragma unroll
        for (int ii = 0; ii < 4; ii++) {
            int i = i0 + ty*4 + ii;
#pragma unroll
            for (int jj = 0; jj < 2; jj++) {
                int j = j0 + tx*2 + jj;
                if (j <= i + MLEN) {
                    int u = j + (QLEN - 1) - i;
                    s[ii][jj] = (s[ii][jj] + bdbase[(size_t)(ty*4+ii)*KLEN + u]) * scale;
                } else {
                    s[ii][jj] = -1e30f;
                }
            }
        }

        float mnew[4], alpha[4];
#pragma unroll
        for (int ii = 0; ii < 4; ii++) {
            float mloc = fmaxf(s[ii][0], s[ii][1]);
#pragma unroll
            for (int off = 8; off; off >>= 1)
                mloc = fmaxf(mloc, __shfl_xor_sync(0xffffffffu, mloc, off));
            mnew[ii]  = fmaxf(mi[ii], mloc);
            alpha[ii] = __expf(mi[ii] - mnew[ii]);
            mi[ii]    = mnew[ii];
        }
#pragma unroll
        for (int ii = 0; ii < 4; ii++) {
            float p0 = __expf(s[ii][0] - mnew[ii]);
            float p1 = __expf(s[ii][1] - mnew[ii]);
            Ps[ty*4+ii][tx*2+0] = p0;
            Ps[ty*4+ii][tx*2+1] = p1;
            float psum = p0 + p1;
#pragma unroll
            for (int off = 8; off; off >>= 1)
                psum += __shfl_xor_sync(0xffffffffu, psum, off);
            li[ii] = li[ii]*alpha[ii] + psum;
#pragma unroll
            for (int dd = 0; dd < 4; dd++) oacc[ii][dd] *= alpha[ii];
        }
        __syncthreads();
        for (int t = tid; t < 2048; t += 256) {
            int jl = t >> 6, d = t & 63;
            KVt[d][jl] = vbase[(size_t)(j0+jl)*64 + d];
        }
        __syncthreads();
#pragma unroll 8
        for (int jl = 0; jl < 32; jl++) {
            float pf[4], vf[4];
#pragma unroll
            for (int ii = 0; ii < 4; ii++) pf[ii] = Ps[ty*4+ii][jl];
#pragma unroll
            for (int dd = 0; dd < 4; dd++) vf[dd] = KVt[dd*16+tx][jl];
#pragma unroll
            for (int ii = 0; ii < 4; ii++)
#pragma unroll
                for (int dd = 0; dd < 4; dd++)
                    oacc[ii][dd] = fmaf(pf[ii], vf[dd], oacc[ii][dd]);
        }
    }

#pragma unroll
    for (int ii = 0; ii < 4; ii++) {
        int i = i0 + ty*4 + ii;
        float inv = 1.f / li[ii];
#pragma unroll
        for (int dd = 0; dd < 4; dd++) {
            int d = dd*16 + tx;
            g_AV[((size_t)i*BSZ + b)*HID + n*64 + d] = oacc[ii][dd] * inv;
        }
    }
}

// ---------------- residual + layernorm (in place on d_out) ----------------
__global__ __launch_bounds__(256) void ln_kernel(
    const float* __restrict__ w, const float* __restrict__ gamma,
    const float* __restrict__ beta, float* __restrict__ out)
{
    const int row = blockIdx.x;
    const int tid = threadIdx.x;
    __shared__ float red[256];
    const float* wrow = w   + (size_t)row * 1024;
    float*       orow = out + (size_t)row * 1024;

    float x[4];
    float sum = 0.f;
#pragma unroll
    for (int l = 0; l < 4; l++) {
        int c = tid + l*256;
        x[l] = wrow[c] + orow[c];
        sum += x[l];
    }
    red[tid] = sum; __syncthreads();
    for (int s = 128; s > 0; s >>= 1) {
        if (tid < s) red[tid] += red[tid + s];
        __syncthreads();
    }
    float mu = red[0] * (1.f/1024.f);
    __syncthreads();

    float vs = 0.f;
#pragma unroll
    for (int l = 0; l < 4; l++) { float dx = x[l] - mu; vs += dx*dx; }
    red[tid] = vs; __syncthreads();
    for (int s = 128; s > 0; s >>= 1) {
        if (tid < s) red[tid] += red[tid + s];
        __syncthreads();
    }
    float rstd = rsqrtf(red[0] * (1.f/1024.f) + 1e-6f);

#pragma unroll
    for (int l = 0; l < 4; l++) {
        int c = tid + l*256;
        orow[c] = (x[l] - mu) * rstd * gamma[c] + beta[c];
    }
}

// ---------------- launch ----------------
extern "C" void kernel_launch(void* const* d_in, const int* in_sizes, int n_in,
                              void* d_out, int out_size)
{
    const float* w      = (const float*)d_in[0];
    const float* r      = (const float*)d_in[1];
    /* d_in[2] = attn_mask: analytic (j > i+MLEN), not needed */
    const float* mems   = (const float*)d_in[3];
    const float* qkvw   = (const float*)d_in[4];
    const float* rw     = (const float*)d_in[5];
    const float* ow     = (const float*)d_in[6];
    const float* rrb    = (const float*)d_in[7];
    const float* rwbias = (const float*)d_in[8];
    const float* gamma  = (const float*)d_in[9];
    const float* beta   = (const float*)d_in[10];
    float* out = (float*)d_out;

    gemm128<0><<<dim3(24, 128), 256>>>(mems, w, qkvw, nullptr, QKV3);
    gemm128<1><<<dim3(8, 8),    256>>>(r, nullptr, rw, nullptr, DM);
    bd_kernel  <<<dim3(8, 256), 256>>>(rrb);
    attn_kernel<<<dim3(8, 256), 256>>>(rwbias);
    gemm128<2><<<dim3(8, 64),   256>>>(nullptr, nullptr, ow, out, DM);
    ln_kernel  <<<8192, 256>>>(w, gamma, beta, out);
}

// round 4
// speedup vs baseline: 1.0675x; 1.0675x over previous
#include <cuda_runtime.h>
#include <cuda_bf16.h>
#include <math.h>
#include <stdint.h>

#define QLEN 512
#define MLEN 512
#define KLEN 1024
#define BSZ  16
#define NH   16
#define DH   64
#define DM   1024
#define HID  1024

// ---------------- scratch (no cudaMalloc allowed) ----------------
__device__ float g_Q [(size_t)BSZ*NH*QLEN*DH];
__device__ float g_K [(size_t)BSZ*NH*KLEN*DH];
__device__ float g_V [(size_t)BSZ*NH*KLEN*DH];
__device__ float g_Rk[(size_t)NH*KLEN*DH];
__device__ float g_BD[(size_t)BSZ*NH*QLEN*KLEN];
__device__ float g_AV[(size_t)QLEN*BSZ*HID];

// ================= HMMA helpers (sm_80+ PTX, works on compute_100) =================
__device__ __forceinline__ uint32_t smem_u32(const void* p) {
    uint32_t a;
    asm("{ .reg .u64 t; cvta.to.shared.u64 t, %1; cvt.u32.u64 %0, t; }" : "=r"(a) : "l"(p));
    return a;
}
__device__ __forceinline__ void ldsm4(uint32_t a[4], uint32_t addr) {
    asm volatile("ldmatrix.sync.aligned.m8n8.x4.shared.b16 {%0,%1,%2,%3}, [%4];"
                 : "=r"(a[0]), "=r"(a[1]), "=r"(a[2]), "=r"(a[3]) : "r"(addr));
}
__device__ __forceinline__ void ldsm2(uint32_t b[2], uint32_t addr) {
    asm volatile("ldmatrix.sync.aligned.m8n8.x2.shared.b16 {%0,%1}, [%2];"
                 : "=r"(b[0]), "=r"(b[1]) : "r"(addr));
}
__device__ __forceinline__ void mma16816(float c[4], const uint32_t a[4], const uint32_t b[2]) {
    asm volatile("mma.sync.aligned.m16n8k16.row.col.f32.bf16.bf16.f32 "
        "{%0,%1,%2,%3}, {%4,%5,%6,%7}, {%8,%9}, {%0,%1,%2,%3};"
        : "+f"(c[0]), "+f"(c[1]), "+f"(c[2]), "+f"(c[3])
        : "r"(a[0]), "r"(a[1]), "r"(a[2]), "r"(a[3]), "r"(b[0]), "r"(b[1]));
}
// split fp32 pair into (hi, lo) bf16x2 words
__device__ __forceinline__ void split2(float a, float b, uint32_t& hi, uint32_t& lo) {
    __nv_bfloat162 h = __floats2bfloat162_rn(a, b);
    float2 hf = __bfloat1622float2(h);
    __nv_bfloat162 l = __floats2bfloat162_rn(a - hf.x, b - hf.y);
    hi = *reinterpret_cast<uint32_t*>(&h);
    lo = *reinterpret_cast<uint32_t*>(&l);
}
__device__ __forceinline__ void split1(float v, __nv_bfloat16& hi, __nv_bfloat16& lo) {
    hi = __float2bfloat16(v);
    lo = __float2bfloat16(v - __bfloat162float(hi));
}

// ---------------- split-bf16 HMMA GEMM, tile 128x128, BK=32, K=1024 ----------------
// MODE 0: A = cat(mems, w), B = qkv_w (ldb 3072), scatter into g_Q/g_K/g_V
// MODE 1: A = r,            B = r_w  (ldb 1024), scatter into g_Rk
// MODE 2: A = g_AV,         B = o_w  (ldb 1024), plain C
//
// smem per buffer (row stride 40 bf16 = 80B, 16B-aligned rows, ldmatrix conflict-free):
//   Ah[128][40] 10240B | Al 10240B | Bh[128n][40k] 10240B | Bl 10240B  = 40960B
// two buffers = 81920 B dynamic smem.
#define GSTRIDE 40
#define GBUF    40960
#define GTC_SMEM (2*GBUF)

template<int MODE>
__global__ __launch_bounds__(256, 1) void gemm_tc(
    const float* __restrict__ A0, const float* __restrict__ A1,
    const float* __restrict__ B, float* __restrict__ C, int ldb)
{
    extern __shared__ char sm[];
    const int tid  = threadIdx.x;
    const int wid  = tid >> 5;
    const int lane = tid & 31;
    const int wm   = wid >> 2;          // 0..1  (64-row warp block)
    const int wn   = wid & 3;           // 0..3  (32-col warp block)
    const int m0   = blockIdx.y * 128;
    const int n0   = blockIdx.x * 128;

    const uint32_t smb = smem_u32(sm);

    float acc[4][4][4];
#pragma unroll
    for (int i = 0; i < 4; i++)
#pragma unroll
        for (int j = 0; j < 4; j++)
#pragma unroll
            for (int q = 0; q < 4; q++) acc[i][j][q] = 0.f;

    // per-thread load indices
    const int amr = tid >> 1;                 // with 2 iters: rows tid>>1? no — see loop
    (void)amr;

    // ldmatrix per-lane base byte offsets (within a buffer)
    // A: row (lane&15), k-half (lane>>4)*8 elems
    const uint32_t a_lm = (uint32_t)((wm*64 + (lane & 15)) * GSTRIDE + (lane >> 4) * 8) * 2;
    // B: row n (lane&7), k-half ((lane>>3)&1)*8
    const uint32_t b_lm = (uint32_t)((wn*32 + (lane & 7)) * GSTRIDE + ((lane >> 3) & 1) * 8) * 2;

    float4 stA[4], stB[4];

    // ---- global load of chunk c into regs ----
    auto load_g = [&](int c) {
        const int k0 = c * 32;
#pragma unroll
        for (int it = 0; it < 4; ++it) {
            int t  = tid + it * 256;          // 0..1023
            int mr = t >> 3;                  // 0..127
            int kf = t & 7;                   // float4 index in 32 k
            int m  = m0 + mr;
            const float* arow;
            if (MODE == 0)
                arow = (m < 8192) ? (A0 + (size_t)m * 1024)
                                  : (A1 + (size_t)(m - 8192) * 1024);
            else if (MODE == 1)
                arow = A0 + (size_t)m * 1024;
            else
                arow = g_AV + (size_t)m * 1024;
            stA[it] = *(const float4*)(arow + k0 + kf * 4);
        }
#pragma unroll
        for (int it = 0; it < 4; ++it) {
            int t  = tid + it * 256;
            int kr = t >> 5;                  // 0..31
            int nf = t & 31;                  // float4 index in 128 n
            stB[it] = *(const float4*)(B + (size_t)(k0 + kr) * ldb + n0 + nf * 4);
        }
    };

    // ---- store staged regs (split hi/lo) into smem buffer bs ----
    auto store_s = [&](int bs) {
        char* buf = sm + bs * GBUF;
        __nv_bfloat16* Ah = (__nv_bfloat16*)(buf);
        __nv_bfloat16* Al = (__nv_bfloat16*)(buf + 10240);
        __nv_bfloat16* Bh = (__nv_bfloat16*)(buf + 20480);
        __nv_bfloat16* Bl = (__nv_bfloat16*)(buf + 30720);
#pragma unroll
        for (int it = 0; it < 4; ++it) {
            int t  = tid + it * 256;
            int mr = t >> 3;
            int kf = t & 7;
            uint32_t h0, l0, h1, l1;
            split2(stA[it].x, stA[it].y, h0, l0);
            split2(stA[it].z, stA[it].w, h1, l1);
            uint32_t off = (uint32_t)(mr * GSTRIDE + kf * 4);
            *(uint2*)(Ah + off) = make_uint2(h0, h1);
            *(uint2*)(Al + off) = make_uint2(l0, l1);
        }
#pragma unroll
        for (int it = 0; it < 4; ++it) {
            int t  = tid + it * 256;
            int kr = t >> 5;
            int nf = t & 31;
            float v[4] = {stB[it].x, stB[it].y, stB[it].z, stB[it].w};
#pragma unroll
            for (int e = 0; e < 4; ++e) {
                int n = nf * 4 + e;
                __nv_bfloat16 hi, lo;
                split1(v[e], hi, lo);
                Bh[n * GSTRIDE + kr] = hi;
                Bl[n * GSTRIDE + kr] = lo;
            }
        }
    };

    // ---- compute on buffer bs ----
    auto compute = [&](int bs) {
        const uint32_t base = smb + bs * GBUF;
#pragma unroll
        for (int s = 0; s < 2; ++s) {
            uint32_t ahi[4][4], alo[4][4], bhi[4][2], blo[4][2];
#pragma unroll
            for (int i = 0; i < 4; ++i) {
                uint32_t off = a_lm + (uint32_t)(i * 16 * GSTRIDE + s * 16) * 2;
                ldsm4(ahi[i], base + off);
                ldsm4(alo[i], base + 10240 + off);
            }
#pragma unroll
            for (int j = 0; j < 4; ++j) {
                uint32_t off = b_lm + (uint32_t)(j * 8 * GSTRIDE + s * 16) * 2;
                ldsm2(bhi[j], base + 20480 + off);
                ldsm2(blo[j], base + 30720 + off);
            }
#pragma unroll
            for (int i = 0; i < 4; ++i)
#pragma unroll
                for (int j = 0; j < 4; ++j) {
                    mma16816(acc[i][j], ahi[i], bhi[j]);
                    mma16816(acc[i][j], ahi[i], blo[j]);
                    mma16816(acc[i][j], alo[i], bhi[j]);
                }
        }
    };

    load_g(0);
    for (int c = 0; c < 32; ++c) {
        const int bs = c & 1;
        store_s(bs);
        __syncthreads();
        if (c + 1 < 32) load_g(c + 1);
        compute(bs);
        __syncthreads();
    }

    // ---- epilogue straight from accumulators ----
    const int g   = lane >> 2;
    const int tig = lane & 3;

    auto storeC = [&](int m, int col, float v0, float v1) {
        if (MODE == 0) {
            int kl = m >> 4, bb = m & 15;
            int sec = col >> 10, hn = (col >> 6) & 15, d = col & 63;
            float2 v = make_float2(v0, v1);
            if (sec == 0) {
                if (kl >= MLEN)
                    *(float2*)&g_Q[((size_t)(bb*NH+hn)*QLEN + (kl-MLEN))*DH + d] = v;
            } else if (sec == 1) {
                *(float2*)&g_K[((size_t)(bb*NH+hn)*KLEN + kl)*DH + d] = v;
            } else {
                *(float2*)&g_V[((size_t)(bb*NH+hn)*KLEN + kl)*DH + d] = v;
            }
        } else if (MODE == 1) {
            int hn = col >> 6, d = col & 63;
            *(float2*)&g_Rk[((size_t)hn*KLEN + m)*DH + d] = make_float2(v0, v1);
        } else {
            *(float2*)&C[(size_t)m * 1024 + col] = make_float2(v0, v1);
        }
    };

#pragma unroll
    for (int i = 0; i < 4; ++i)
#pragma unroll
        for (int j = 0; j < 4; ++j) {
            int m   = m0 + wm*64 + i*16 + g;
            int col = n0 + wn*32 + j*8 + 2*tig;
            storeC(m,     col, acc[i][j][0], acc[i][j][1]);
            storeC(m + 8, col, acc[i][j][2], acc[i][j][3]);
        }
}

// ---------------- BD GEMM (skips never-read lower tiles) ----------------
__global__ __launch_bounds__(256) void bd_kernel(const float* __restrict__ rrb)
{
    const int i0 = blockIdx.x * 64;
    const int bn = blockIdx.y;
    const int b = bn >> 4, n = bn & 15;
    __shared__ float Qs[64][65];
    __shared__ float Rs[64][65];
    const int tid = threadIdx.x;
    const int ty = tid >> 4, tx = tid & 15;

    const float* qbase = g_Q + ((size_t)(b*NH+n)*QLEN + i0) * DH;
    for (int t = tid; t < 64*64; t += 256) {
        int r = t >> 6, d = t & 63;
        Qs[r][d] = qbase[r*64 + d] + rrb[n*64 + d];
    }
    float* outbase = g_BD + ((size_t)(b*NH+n)*QLEN + i0) * KLEN;

    int u0s = 448 - i0; if (u0s < 0) u0s = 0;   // only u >= 511-(i0+63) is ever read
    for (int u0 = u0s; u0 < KLEN; u0 += 64) {
        __syncthreads();
        const float* rkbase = g_Rk + ((size_t)n*KLEN + u0) * DH;
        for (int t = tid; t < 64*64; t += 256) {
            int r = t >> 6, d = t & 63;
            Rs[r][d] = rkbase[r*64 + d];
        }
        __syncthreads();
        float acc[4][4] = {};
#pragma unroll
        for (int d = 0; d < 64; d++) {
            float qf[4], rf[4];
#pragma unroll
            for (int ii = 0; ii < 4; ii++) qf[ii] = Qs[ty*4+ii][d];
#pragma unroll
            for (int uu = 0; uu < 4; uu++) rf[uu] = Rs[tx*4+uu][d];
#pragma unroll
            for (int ii = 0; ii < 4; ii++)
#pragma unroll
                for (int uu = 0; uu < 4; uu++)
                    acc[ii][uu] = fmaf(qf[ii], rf[uu], acc[ii][uu]);
        }
#pragma unroll
        for (int ii = 0; ii < 4; ii++)
#pragma unroll
            for (int uu = 0; uu < 4; uu++)
                outbase[(size_t)(ty*4+ii)*KLEN + u0 + tx*4 + uu] = acc[ii][uu];
    }
}

// ---------------- fused attention with online softmax ----------------
__global__ __launch_bounds__(256) void attn_kernel(const float* __restrict__ rwb)
{
    const int i0 = blockIdx.x * 64;
    const int bn = blockIdx.y;
    const int b = bn >> 4, n = bn & 15;
    const int tid = threadIdx.x;
    const int ty = tid >> 4, tx = tid & 15;

    __shared__ float Qs [64][65];
    __shared__ float KVt[64][33];
    __shared__ float Ps [64][33];

    const float* qbase = g_Q + ((size_t)(b*NH+n)*QLEN + i0) * DH;
    for (int t = tid; t < 4096; t += 256) {
        int r = t >> 6, d = t & 63;
        Qs[r][d] = qbase[r*64 + d] + rwb[n*64 + d];
    }

    float mi[4], li[4], oacc[4][4];
#pragma unroll
    for (int ii = 0; ii < 4; ii++) {
        mi[ii] = -INFINITY; li[ii] = 0.f;
#pragma unroll
        for (int dd = 0; dd < 4; dd++) oacc[ii][dd] = 0.f;
    }

    const float* kbase  = g_K + (size_t)(b*NH+n)*KLEN*DH;
    const float* vbase  = g_V + (size_t)(b*NH+n)*KLEN*DH;
    const float* bdbase = g_BD + ((size_t)(b*NH+n)*QLEN + i0) * KLEN;
    const int   jmax  = i0 + 576;
    const float scale = 0.125f;

    for (int j0 = 0; j0 < jmax; j0 += 32) {
        __syncthreads();
        for (int t = tid; t < 2048; t += 256) {
            int jl = t >> 6, d = t & 63;
            KVt[d][jl] = kbase[(size_t)(j0+jl)*64 + d];
        }
        __syncthreads();

        float s[4][2];
#pragma unroll
        for (int ii = 0; ii < 4; ii++) { s[ii][0] = 0.f; s[ii][1] = 0.f; }
#pragma unroll
        for (int d = 0; d < 64; d++) {
            float qf[4];
#pragma unroll
            for (int ii = 0; ii < 4; ii++) qf[ii] = Qs[ty*4+ii][d];
            float k0f = KVt[d][tx*2+0];
            float k1f = KVt[d][tx*2+1];
#pragma unroll
            for (int ii = 0; ii < 4; ii++) {
                s[ii][0] = fmaf(qf[ii], k0f, s[ii][0]);
                s[ii][1] = fmaf(qf[ii], k1f, s[ii][1]);
            }
        }
#pragma unroll
        for (int ii = 0; ii < 4; ii++) {
            int i = i0 + ty*4 + ii;
#pragma unroll
            for (int jj = 0; jj < 2; jj++) {
                int j = j0 + tx*2 + jj;
                if (j <= i + MLEN) {
                    int u = j + (QLEN - 1) - i;
                    s[ii][jj] = (s[ii][jj] + bdbase[(size_t)(ty*4+ii)*KLEN + u]) * scale;
                } else {
                    s[ii][jj] = -1e30f;
                }
            }
        }

        float mnew[4], alpha[4];
#pragma unroll
        for (int ii = 0; ii < 4; ii++) {
            float mloc = fmaxf(s[ii][0], s[ii][1]);
#pragma unroll
            for (int off = 8; off; off >>= 1)
                mloc = fmaxf(mloc, __shfl_xor_sync(0xffffffffu, mloc, off));
            mnew[ii]  = fmaxf(mi[ii], mloc);
            alpha[ii] = __expf(mi[ii] - mnew[ii]);
            mi[ii]    = mnew[ii];
        }
#pragma unroll
        for (int ii = 0; ii < 4; ii++) {
            float p0 = __expf(s[ii][0] - mnew[ii]);
            float p1 = __expf(s[ii][1] - mnew[ii]);
            Ps[ty*4+ii][tx*2+0] = p0;
            Ps[ty*4+ii][tx*2+1] = p1;
            float psum = p0 + p1;
#pragma unroll
            for (int off = 8; off; off >>= 1)
                psum += __shfl_xor_sync(0xffffffffu, psum, off);
            li[ii] = li[ii]*alpha[ii] + psum;
#pragma unroll
            for (int dd = 0; dd < 4; dd++) oacc[ii][dd] *= alpha[ii];
        }
        __syncthreads();
        for (int t = tid; t < 2048; t += 256) {
            int jl = t >> 6, d = t & 63;
            KVt[d][jl] = vbase[(size_t)(j0+jl)*64 + d];
        }
        __syncthreads();
#pragma unroll 8
        for (int jl = 0; jl < 32; jl++) {
            float pf[4], vf[4];
#pragma unroll
            for (int ii = 0; ii < 4; ii++) pf[ii] = Ps[ty*4+ii][jl];
#pragma unroll
            for (int dd = 0; dd < 4; dd++) vf[dd] = KVt[dd*16+tx][jl];
#pragma unroll
            for (int ii = 0; ii < 4; ii++)
#pragma unroll
                for (int dd = 0; dd < 4; dd++)
                    oacc[ii][dd] = fmaf(pf[ii], vf[dd], oacc[ii][dd]);
        }
    }

#pragma unroll
    for (int ii = 0; ii < 4; ii++) {
        int i = i0 + ty*4 + ii;
        float inv = 1.f / li[ii];
#pragma unroll
        for (int dd = 0; dd < 4; dd++) {
            int d = dd*16 + tx;
            g_AV[((size_t)i*BSZ + b)*HID + n*64 + d] = oacc[ii][dd] * inv;
        }
    }
}

// ---------------- residual + layernorm ----------------
__global__ __launch_bounds__(256) void ln_kernel(
    const float* __restrict__ w, const float* __restrict__ gamma,
    const float* __restrict__ beta, float* __restrict__ out)
{
    const int row = blockIdx.x;
    const int tid = threadIdx.x;
    __shared__ float red[256];
    const float* wrow = w   + (size_t)row * 1024;
    float*       orow = out + (size_t)row * 1024;

    float x[4];
    float sum = 0.f;
#pragma unroll
    for (int l = 0; l < 4; l++) {
        int c = tid + l*256;
        x[l] = wrow[c] + orow[c];
        sum += x[l];
    }
    red[tid] = sum; __syncthreads();
    for (int s = 128; s > 0; s >>= 1) {
        if (tid < s) red[tid] += red[tid + s];
        __syncthreads();
    }
    float mu = red[0] * (1.f/1024.f);
    __syncthreads();

    float vs = 0.f;
#pragma unroll
    for (int l = 0; l < 4; l++) { float dx = x[l] - mu; vs += dx*dx; }
    red[tid] = vs; __syncthreads();
    for (int s = 128; s > 0; s >>= 1) {
        if (tid < s) red[tid] += red[tid + s];
        __syncthreads();
    }
    float rstd = rsqrtf(red[0] * (1.f/1024.f) + 1e-6f);

#pragma unroll
    for (int l = 0; l < 4; l++) {
        int c = tid + l*256;
        orow[c] = (x[l] - mu) * rstd * gamma[c] + beta[c];
    }
}

// ---------------- launch ----------------
extern "C" void kernel_launch(void* const* d_in, const int* in_sizes, int n_in,
                              void* d_out, int out_size)
{
    const float* w      = (const float*)d_in[0];
    const float* r      = (const float*)d_in[1];
    /* d_in[2] = attn_mask: analytic (j > i+MLEN), not needed */
    const float* mems   = (const float*)d_in[3];
    const float* qkvw   = (const float*)d_in[4];
    const float* rw     = (const float*)d_in[5];
    const float* ow     = (const float*)d_in[6];
    const float* rrb    = (const float*)d_in[7];
    const float* rwbias = (const float*)d_in[8];
    const float* gamma  = (const float*)d_in[9];
    const float* beta   = (const float*)d_in[10];
    float* out = (float*)d_out;

    cudaFuncSetAttribute(gemm_tc<0>, cudaFuncAttributeMaxDynamicSharedMemorySize, GTC_SMEM);
    cudaFuncSetAttribute(gemm_tc<1>, cudaFuncAttributeMaxDynamicSharedMemorySize, GTC_SMEM);
    cudaFuncSetAttribute(gemm_tc<2>, cudaFuncAttributeMaxDynamicSharedMemorySize, GTC_SMEM);

    gemm_tc<0><<<dim3(24, 128), 256, GTC_SMEM>>>(mems, w, qkvw, nullptr, 3072);
    gemm_tc<1><<<dim3(8, 8),    256, GTC_SMEM>>>(r, nullptr, rw, nullptr, 1024);
    bd_kernel  <<<dim3(8, 256), 256>>>(rrb);
    attn_kernel<<<dim3(8, 256), 256>>>(rwbias);
    gemm_tc<2><<<dim3(8, 64),   256, GTC_SMEM>>>(nullptr, nullptr, ow, out, 1024);
    ln_kernel  <<<8192, 256>>>(w, gamma, beta, out);
}

// round 5
// speedup vs baseline: 1.9741x; 1.8493x over previous
#include <cuda_runtime.h>
#include <cuda_bf16.h>
#include <math.h>
#include <stdint.h>

#define QLEN 512
#define MLEN 512
#define KLEN 1024
#define BSZ  16
#define NH   16
#define DH   64
#define DM   1024
#define HID  1024

// ---------------- fp32 scratch ----------------
__device__ float g_Q [(size_t)BSZ*NH*QLEN*DH];
__device__ float g_K [(size_t)BSZ*NH*KLEN*DH];
__device__ float g_V [(size_t)BSZ*NH*KLEN*DH];
__device__ float g_Rk[(size_t)NH*KLEN*DH];
__device__ float g_BD[(size_t)BSZ*NH*QLEN*KLEN];
__device__ float g_AV[(size_t)QLEN*BSZ*HID];

// ---------------- pre-split bf16 hi/lo scratch ----------------
__device__ __nv_bfloat16 g_Ah [(size_t)16384*1024];   // cat(mems,w) hi
__device__ __nv_bfloat16 g_Al [(size_t)16384*1024];
__device__ __nv_bfloat16 g_Wth[(size_t)3072*1024];    // qkv_w^T [n][k]
__device__ __nv_bfloat16 g_Wtl[(size_t)3072*1024];
__device__ __nv_bfloat16 g_R2h[(size_t)1024*1024];    // r
__device__ __nv_bfloat16 g_R2l[(size_t)1024*1024];
__device__ __nv_bfloat16 g_RWth[(size_t)1024*1024];   // r_w^T
__device__ __nv_bfloat16 g_RWtl[(size_t)1024*1024];
__device__ __nv_bfloat16 g_OWth[(size_t)1024*1024];   // o_w^T
__device__ __nv_bfloat16 g_OWtl[(size_t)1024*1024];
__device__ __nv_bfloat16 g_AVh[(size_t)8192*1024];    // attn_vec
__device__ __nv_bfloat16 g_AVl[(size_t)8192*1024];

// ================= helpers =================
__device__ __forceinline__ uint32_t smem_u32(const void* p) {
    uint32_t a;
    asm("{ .reg .u64 t; cvta.to.shared.u64 t, %1; cvt.u32.u64 %0, t; }" : "=r"(a) : "l"(p));
    return a;
}
__device__ __forceinline__ void ldsm4(uint32_t a[4], uint32_t addr) {
    asm volatile("ldmatrix.sync.aligned.m8n8.x4.shared.b16 {%0,%1,%2,%3}, [%4];"
                 : "=r"(a[0]), "=r"(a[1]), "=r"(a[2]), "=r"(a[3]) : "r"(addr));
}
__device__ __forceinline__ void ldsm2(uint32_t b[2], uint32_t addr) {
    asm volatile("ldmatrix.sync.aligned.m8n8.x2.shared.b16 {%0,%1}, [%2];"
                 : "=r"(b[0]), "=r"(b[1]) : "r"(addr));
}
__device__ __forceinline__ void mma16816(float c[4], const uint32_t a[4], const uint32_t b[2]) {
    asm volatile("mma.sync.aligned.m16n8k16.row.col.f32.bf16.bf16.f32 "
        "{%0,%1,%2,%3}, {%4,%5,%6,%7}, {%8,%9}, {%0,%1,%2,%3};"
        : "+f"(c[0]), "+f"(c[1]), "+f"(c[2]), "+f"(c[3])
        : "r"(a[0]), "r"(a[1]), "r"(a[2]), "r"(a[3]), "r"(b[0]), "r"(b[1]));
}
__device__ __forceinline__ void cpa16(uint32_t dst, const void* src) {
    asm volatile("cp.async.cg.shared.global [%0], [%1], 16;" :: "r"(dst), "l"(src));
}
#define CPA_COMMIT() asm volatile("cp.async.commit_group;")
#define CPA_WAIT1()  asm volatile("cp.async.wait_group 1;")
#define CPA_WAIT0()  asm volatile("cp.async.wait_group 0;")

__device__ __forceinline__ void split1(float v, __nv_bfloat16& hi, __nv_bfloat16& lo) {
    hi = __float2bfloat16(v);
    lo = __float2bfloat16(v - __bfloat162float(hi));
}

// ---------------- split kernels (run once per tensor) ----------------
__global__ __launch_bounds__(256) void split_k(
    const float* __restrict__ src, __nv_bfloat16* __restrict__ h,
    __nv_bfloat16* __restrict__ l, int n4)
{
    int i = blockIdx.x * 256 + threadIdx.x;
    if (i >= n4) return;
    float4 v = ((const float4*)src)[i];
    __nv_bfloat16 hh[4], ll[4];
    split1(v.x, hh[0], ll[0]); split1(v.y, hh[1], ll[1]);
    split1(v.z, hh[2], ll[2]); split1(v.w, hh[3], ll[3]);
    ((uint2*)h)[i] = *(uint2*)hh;
    ((uint2*)l)[i] = *(uint2*)ll;
}

// transpose + split: src [K][N] fp32 -> th/tl [N][K] bf16
__global__ __launch_bounds__(256) void tsplit_k(
    const float* __restrict__ src, __nv_bfloat16* __restrict__ th,
    __nv_bfloat16* __restrict__ tl, int K, int N)
{
    __shared__ float tile[32][33];
    const int n0 = blockIdx.x * 32, k0 = blockIdx.y * 32;
    const int tx = threadIdx.x & 31, ty0 = threadIdx.x >> 5;
#pragma unroll
    for (int it = 0; it < 4; ++it) {
        int ty = ty0 + it * 8;
        tile[ty][tx] = src[(size_t)(k0 + ty) * N + n0 + tx];
    }
    __syncthreads();
#pragma unroll
    for (int it = 0; it < 4; ++it) {
        int ty = ty0 + it * 8;               // n index
        float v = tile[tx][ty];              // [k][n] -> transposed
        __nv_bfloat16 hi, lo; split1(v, hi, lo);
        th[(size_t)(n0 + ty) * K + k0 + tx] = hi;
        tl[(size_t)(n0 + ty) * K + k0 + tx] = lo;
    }
}

// ---------------- split-bf16 HMMA GEMM, tile 128x128, BK=64, K=1024 ----------------
// smem per stage 64KB: Ah 16K | Al 16K | Bh 16K | Bl 16K. 2 stages = 128KB.
// XOR-swizzled 128B rows: phys = row*128 + ((chunk ^ (row&7))*16)
#define GSTG 65536
#define GTC_SMEM (2*GSTG)

template<int MODE>
__global__ __launch_bounds__(256, 1) void gemm_bf(
    const __nv_bfloat16* __restrict__ Ah, const __nv_bfloat16* __restrict__ Al,
    const __nv_bfloat16* __restrict__ Bh, const __nv_bfloat16* __restrict__ Bl,
    float* __restrict__ C)
{
    const int m0 = blockIdx.y * 128;
    const int n0 = blockIdx.x * 128;
    if (MODE == 0 && n0 < 1024 && m0 < 8192) return;   // Q of mems: dead

    extern __shared__ char sm[];
    const int tid  = threadIdx.x;
    const int wid  = tid >> 5;
    const int lane = tid & 31;
    const int wm   = wid >> 2;
    const int wn   = wid & 3;
    const uint32_t smb = smem_u32(sm);

    float acc[4][4][4];
#pragma unroll
    for (int i = 0; i < 4; i++)
#pragma unroll
        for (int j = 0; j < 4; j++)
#pragma unroll
            for (int q = 0; q < 4; q++) acc[i][j][q] = 0.f;

    const int lr = tid >> 3;        // row 0..31 step; with 4 iters covers 128
    const int lc = tid & 7;         // 16B chunk 0..7

    auto load_stage = [&](int c, int stg) {
        const int k0 = c * 64;
        const uint32_t base = smb + stg * GSTG;
#pragma unroll
        for (int it = 0; it < 4; ++it) {
            int r = lr + it * 32;
            uint32_t dst = base + (uint32_t)(r * 128 + ((lc ^ (r & 7)) << 4));
            const size_t aoff = (size_t)(m0 + r) * 1024 + k0 + lc * 8;
            const size_t boff = (size_t)(n0 + r) * 1024 + k0 + lc * 8;
            cpa16(dst,          Ah + aoff);
            cpa16(dst + 16384,  Al + aoff);
            cpa16(dst + 32768,  Bh + boff);
            cpa16(dst + 49152,  Bl + boff);
        }
        CPA_COMMIT();
    };

    auto compute = [&](int stg) {
        const uint32_t base = smb + stg * GSTG;
#pragma unroll
        for (int s = 0; s < 4; ++s) {
            uint32_t ahi[4][4], alo[4][4], bhi[4][2], blo[4][2];
#pragma unroll
            for (int i = 0; i < 4; ++i) {
                int row = wm * 64 + i * 16 + (lane & 15);
                int ch  = s * 2 + (lane >> 4);
                uint32_t addr = base + (uint32_t)(row * 128 + ((ch ^ (row & 7)) << 4));
                ldsm4(ahi[i], addr);
                ldsm4(alo[i], addr + 16384);
            }
#pragma unroll
            for (int j = 0; j < 4; ++j) {
                int row = wn * 32 + j * 8 + (lane & 7);
                int ch  = s * 2 + ((lane >> 3) & 1);
                uint32_t addr = base + 32768u + (uint32_t)(row * 128 + ((ch ^ (row & 7)) << 4));
                ldsm2(bhi[j], addr);
                ldsm2(blo[j], addr + 16384);
            }
#pragma unroll
            for (int i = 0; i < 4; ++i)
#pragma unroll
                for (int j = 0; j < 4; ++j) {
                    mma16816(acc[i][j], ahi[i], bhi[j]);
                    mma16816(acc[i][j], ahi[i], blo[j]);
                    mma16816(acc[i][j], alo[i], bhi[j]);
                }
        }
    };

    load_stage(0, 0);
    load_stage(1, 1);
#pragma unroll 1
    for (int c = 0; c < 16; ++c) {
        CPA_WAIT1();
        __syncthreads();
        compute(c & 1);
        __syncthreads();
        if (c + 2 < 16) load_stage(c + 2, c & 1);
        else            CPA_COMMIT();          // keep group count in lockstep
    }

    // ---- epilogue straight from accumulators ----
    const int g   = lane >> 2;
    const int tig = lane & 3;

    auto storeC = [&](int m, int col, float v0, float v1) {
        if (MODE == 0) {
            int kl = m >> 4, bb = m & 15;
            int sec = col >> 10, hn = (col >> 6) & 15, d = col & 63;
            float2 v = make_float2(v0, v1);
            if (sec == 0) {
                if (kl >= MLEN)
                    *(float2*)&g_Q[((size_t)(bb*NH+hn)*QLEN + (kl-MLEN))*DH + d] = v;
            } else if (sec == 1) {
                *(float2*)&g_K[((size_t)(bb*NH+hn)*KLEN + kl)*DH + d] = v;
            } else {
                *(float2*)&g_V[((size_t)(bb*NH+hn)*KLEN + kl)*DH + d] = v;
            }
        } else if (MODE == 1) {
            int hn = col >> 6, d = col & 63;
            *(float2*)&g_Rk[((size_t)hn*KLEN + m)*DH + d] = make_float2(v0, v1);
        } else {
            *(float2*)&C[(size_t)m * 1024 + col] = make_float2(v0, v1);
        }
    };

#pragma unroll
    for (int i = 0; i < 4; ++i)
#pragma unroll
        for (int j = 0; j < 4; ++j) {
            int m   = m0 + wm*64 + i*16 + g;
            int col = n0 + wn*32 + j*8 + 2*tig;
            storeC(m,     col, acc[i][j][0], acc[i][j][1]);
            storeC(m + 8, col, acc[i][j][2], acc[i][j][3]);
        }
}

// ---------------- BD GEMM (skips never-read lower tiles) ----------------
__global__ __launch_bounds__(256) void bd_kernel(const float* __restrict__ rrb)
{
    const int i0 = blockIdx.x * 64;
    const int bn = blockIdx.y;
    const int b = bn >> 4, n = bn & 15;
    __shared__ float Qs[64][65];
    __shared__ float Rs[64][65];
    const int tid = threadIdx.x;
    const int ty = tid >> 4, tx = tid & 15;

    const float* qbase = g_Q + ((size_t)(b*NH+n)*QLEN + i0) * DH;
    for (int t = tid; t < 64*64; t += 256) {
        int r = t >> 6, d = t & 63;
        Qs[r][d] = qbase[r*64 + d] + rrb[n*64 + d];
    }
    float* outbase = g_BD + ((size_t)(b*NH+n)*QLEN + i0) * KLEN;

    int u0s = 448 - i0; if (u0s < 0) u0s = 0;
    for (int u0 = u0s; u0 < KLEN; u0 += 64) {
        __syncthreads();
        const float* rkbase = g_Rk + ((size_t)n*KLEN + u0) * DH;
        for (int t = tid; t < 64*64; t += 256) {
            int r = t >> 6, d = t & 63;
            Rs[r][d] = rkbase[r*64 + d];
        }
        __syncthreads();
        float acc[4][4] = {};
#pragma unroll
        for (int d = 0; d < 64; d++) {
            float qf[4], rf[4];
#pragma unroll
            for (int ii = 0; ii < 4; ii++) qf[ii] = Qs[ty*4+ii][d];
#pragma unroll
            for (int uu = 0; uu < 4; uu++) rf[uu] = Rs[tx*4+uu][d];
#pragma unroll
            for (int ii = 0; ii < 4; ii++)
#pragma unroll
                for (int uu = 0; uu < 4; uu++)
                    acc[ii][uu] = fmaf(qf[ii], rf[uu], acc[ii][uu]);
        }
#pragma unroll
        for (int ii = 0; ii < 4; ii++)
#pragma unroll
            for (int uu = 0; uu < 4; uu++)
                outbase[(size_t)(ty*4+ii)*KLEN + u0 + tx*4 + uu] = acc[ii][uu];
    }
}

// ---------------- fused attention with online softmax ----------------
__global__ __launch_bounds__(256) void attn_kernel(const float* __restrict__ rwb)
{
    const int i0 = blockIdx.x * 64;
    const int bn = blockIdx.y;
    const int b = bn >> 4, n = bn & 15;
    const int tid = threadIdx.x;
    const int ty = tid >> 4, tx = tid & 15;

    __shared__ float Qs [64][65];
    __shared__ float KVt[64][33];
    __shared__ float Ps [64][33];

    const float* qbase = g_Q + ((size_t)(b*NH+n)*QLEN + i0) * DH;
    for (int t = tid; t < 4096; t += 256) {
        int r = t >> 6, d = t & 63;
        Qs[r][d] = qbase[r*64 + d] + rwb[n*64 + d];
    }

    float mi[4], li[4], oacc[4][4];
#pragma unroll
    for (int ii = 0; ii < 4; ii++) {
        mi[ii] = -INFINITY; li[ii] = 0.f;
#pragma unroll
        for (int dd = 0; dd < 4; dd++) oacc[ii][dd] = 0.f;
    }

    const float* kbase  = g_K + (size_t)(b*NH+n)*KLEN*DH;
    const float* vbase  = g_V + (size_t)(b*NH+n)*KLEN*DH;
    const float* bdbase = g_BD + ((size_t)(b*NH+n)*QLEN + i0) * KLEN;
    const int   jmax  = i0 + 576;
    const float scale = 0.125f;

    for (int j0 = 0; j0 < jmax; j0 += 32) {
        __syncthreads();
        for (int t = tid; t < 2048; t += 256) {
            int jl = t >> 6, d = t & 63;
            KVt[d][jl] = kbase[(size_t)(j0+jl)*64 + d];
        }
        __syncthreads();

        float s[4][2];
#pragma unroll
        for (int ii = 0; ii < 4; ii++) { s[ii][0] = 0.f; s[ii][1] = 0.f; }
#pragma unroll
        for (int d = 0; d < 64; d++) {
            float qf[4];
#pragma unroll
            for (int ii = 0; ii < 4; ii++) qf[ii] = Qs[ty*4+ii][d];
            float k0f = KVt[d][tx*2+0];
            float k1f = KVt[d][tx*2+1];
#pragma unroll
            for (int ii = 0; ii < 4; ii++) {
                s[ii][0] = fmaf(qf[ii], k0f, s[ii][0]);
                s[ii][1] = fmaf(qf[ii], k1f, s[ii][1]);
            }
        }
#pragma unroll
        for (int ii = 0; ii < 4; ii++) {
            int i = i0 + ty*4 + ii;
#pragma unroll
            for (int jj = 0; jj < 2; jj++) {
                int j = j0 + tx*2 + jj;
                if (j <= i + MLEN) {
                    int u = j + (QLEN - 1) - i;
                    s[ii][jj] = (s[ii][jj] + bdbase[(size_t)(ty*4+ii)*KLEN + u]) * scale;
                } else {
                    s[ii][jj] = -1e30f;
                }
            }
        }

        float mnew[4], alpha[4];
#pragma unroll
        for (int ii = 0; ii < 4; ii++) {
            float mloc = fmaxf(s[ii][0], s[ii][1]);
#pragma unroll
            for (int off = 8; off; off >>= 1)
                mloc = fmaxf(mloc, __shfl_xor_sync(0xffffffffu, mloc, off));
            mnew[ii]  = fmaxf(mi[ii], mloc);
            alpha[ii] = __expf(mi[ii] - mnew[ii]);
            mi[ii]    = mnew[ii];
        }
#pragma unroll
        for (int ii = 0; ii < 4; ii++) {
            float p0 = __expf(s[ii][0] - mnew[ii]);
            float p1 = __expf(s[ii][1] - mnew[ii]);
            Ps[ty*4+ii][tx*2+0] = p0;
            Ps[ty*4+ii][tx*2+1] = p1;
            float psum = p0 + p1;
#pragma unroll
            for (int off = 8; off; off >>= 1)
                psum += __shfl_xor_sync(0xffffffffu, psum, off);
            li[ii] = li[ii]*alpha[ii] + psum;
#pragma unroll
            for (int dd = 0; dd < 4; dd++) oacc[ii][dd] *= alpha[ii];
        }
        __syncthreads();
        for (int t = tid; t < 2048; t += 256) {
            int jl = t >> 6, d = t & 63;
            KVt[d][jl] = vbase[(size_t)(j0+jl)*64 + d];
        }
        __syncthreads();
#pragma unroll 8
        for (int jl = 0; jl < 32; jl++) {
            float pf[4], vf[4];
#pragma unroll
            for (int ii = 0; ii < 4; ii++) pf[ii] = Ps[ty*4+ii][jl];
#pragma unroll
            for (int dd = 0; dd < 4; dd++) vf[dd] = KVt[dd*16+tx][jl];
#pragma unroll
            for (int ii = 0; ii < 4; ii++)
#pragma unroll
                for (int dd = 0; dd < 4; dd++)
                    oacc[ii][dd] = fmaf(pf[ii], vf[dd], oacc[ii][dd]);
        }
    }

#pragma unroll
    for (int ii = 0; ii < 4; ii++) {
        int i = i0 + ty*4 + ii;
        float inv = 1.f / li[ii];
#pragma unroll
        for (int dd = 0; dd < 4; dd++) {
            int d = dd*16 + tx;
            g_AV[((size_t)i*BSZ + b)*HID + n*64 + d] = oacc[ii][dd] * inv;
        }
    }
}

// ---------------- residual + layernorm ----------------
__global__ __launch_bounds__(256) void ln_kernel(
    const float* __restrict__ w, const float* __restrict__ gamma,
    const float* __restrict__ beta, float* __restrict__ out)
{
    const int row = blockIdx.x;
    const int tid = threadIdx.x;
    __shared__ float red[256];
    const float* wrow = w   + (size_t)row * 1024;
    float*       orow = out + (size_t)row * 1024;

    float x[4];
    float sum = 0.f;
#pragma unroll
    for (int l = 0; l < 4; l++) {
        int c = tid + l*256;
        x[l] = wrow[c] + orow[c];
        sum += x[l];
    }
    red[tid] = sum; __syncthreads();
    for (int s = 128; s > 0; s >>= 1) {
        if (tid < s) red[tid] += red[tid + s];
        __syncthreads();
    }
    float mu = red[0] * (1.f/1024.f);
    __syncthreads();

    float vs = 0.f;
#pragma unroll
    for (int l = 0; l < 4; l++) { float dx = x[l] - mu; vs += dx*dx; }
    red[tid] = vs; __syncthreads();
    for (int s = 128; s > 0; s >>= 1) {
        if (tid < s) red[tid] += red[tid + s];
        __syncthreads();
    }
    float rstd = rsqrtf(red[0] * (1.f/1024.f) + 1e-6f);

#pragma unroll
    for (int l = 0; l < 4; l++) {
        int c = tid + l*256;
        orow[c] = (x[l] - mu) * rstd * gamma[c] + beta[c];
    }
}

// ---------------- launch ----------------
extern "C" void kernel_launch(void* const* d_in, const int* in_sizes, int n_in,
                              void* d_out, int out_size)
{
    const float* w      = (const float*)d_in[0];
    const float* r      = (const float*)d_in[1];
    const float* mems   = (const float*)d_in[3];
    const float* qkvw   = (const float*)d_in[4];
    const float* rw     = (const float*)d_in[5];
    const float* ow     = (const float*)d_in[6];
    const float* rrb    = (const float*)d_in[7];
    const float* rwbias = (const float*)d_in[8];
    const float* gamma  = (const float*)d_in[9];
    const float* beta   = (const float*)d_in[10];
    float* out = (float*)d_out;

    __nv_bfloat16 *Ah, *Al, *Wth, *Wtl, *R2h, *R2l, *RWth, *RWtl, *OWth, *OWtl, *AVh, *AVl;
    float *AV;
    cudaGetSymbolAddress((void**)&Ah,  g_Ah);  cudaGetSymbolAddress((void**)&Al,  g_Al);
    cudaGetSymbolAddress((void**)&Wth, g_Wth); cudaGetSymbolAddress((void**)&Wtl, g_Wtl);
    cudaGetSymbolAddress((void**)&R2h, g_R2h); cudaGetSymbolAddress((void**)&R2l, g_R2l);
    cudaGetSymbolAddress((void**)&RWth,g_RWth);cudaGetSymbolAddress((void**)&RWtl,g_RWtl);
    cudaGetSymbolAddress((void**)&OWth,g_OWth);cudaGetSymbolAddress((void**)&OWtl,g_OWtl);
    cudaGetSymbolAddress((void**)&AVh, g_AVh); cudaGetSymbolAddress((void**)&AVl, g_AVl);
    cudaGetSymbolAddress((void**)&AV,  g_AV);

    cudaFuncSetAttribute(gemm_bf<0>, cudaFuncAttributeMaxDynamicSharedMemorySize, GTC_SMEM);
    cudaFuncSetAttribute(gemm_bf<1>, cudaFuncAttributeMaxDynamicSharedMemorySize, GTC_SMEM);
    cudaFuncSetAttribute(gemm_bf<2>, cudaFuncAttributeMaxDynamicSharedMemorySize, GTC_SMEM);

    // pre-split inputs
    split_k <<<8192, 256>>>(mems, Ah, Al, 2097152);                         // cat rows 0..8191
    split_k <<<8192, 256>>>(w, Ah + (size_t)8192*1024, Al + (size_t)8192*1024, 2097152);
    tsplit_k<<<dim3(96, 32), 256>>>(qkvw, Wth, Wtl, 1024, 3072);
    split_k <<<1024, 256>>>(r, R2h, R2l, 262144);
    tsplit_k<<<dim3(32, 32), 256>>>(rw, RWth, RWtl, 1024, 1024);
    tsplit_k<<<dim3(32, 32), 256>>>(ow, OWth, OWtl, 1024, 1024);

    gemm_bf<0><<<dim3(24, 128), 256, GTC_SMEM>>>(Ah, Al, Wth, Wtl, nullptr);
    gemm_bf<1><<<dim3(8, 8),    256, GTC_SMEM>>>(R2h, R2l, RWth, RWtl, nullptr);
    bd_kernel  <<<dim3(8, 256), 256>>>(rrb);
    attn_kernel<<<dim3(8, 256), 256>>>(rwbias);
    split_k <<<8192, 256>>>(AV, AVh, AVl, 2097152);
    gemm_bf<2><<<dim3(8, 64),   256, GTC_SMEM>>>(AVh, AVl, OWth, OWtl, out);
    ln_kernel  <<<8192, 256>>>(w, gamma, beta, out);
}

// round 6
// speedup vs baseline: 3.1005x; 1.5706x over previous
#include <cuda_runtime.h>
#include <cuda_bf16.h>
#include <math.h>
#include <stdint.h>

#define QLEN 512
#define MLEN 512
#define KLEN 1024
#define BSZ  16
#define NH   16
#define DH   64
#define DM   1024
#define HID  1024

// ---------------- fp32 scratch ----------------
__device__ float g_Q [(size_t)BSZ*NH*QLEN*DH];
__device__ float g_K [(size_t)BSZ*NH*KLEN*DH];
__device__ float g_V [(size_t)BSZ*NH*KLEN*DH];
__device__ float g_Rk[(size_t)NH*KLEN*DH];
__device__ float g_BD[(size_t)BSZ*NH*QLEN*KLEN];
__device__ float g_AV[(size_t)QLEN*BSZ*HID];

// ---------------- pre-split bf16 hi/lo scratch (GEMM inputs) ----------------
__device__ __nv_bfloat16 g_Ah [(size_t)16384*1024];
__device__ __nv_bfloat16 g_Al [(size_t)16384*1024];
__device__ __nv_bfloat16 g_Wth[(size_t)3072*1024];
__device__ __nv_bfloat16 g_Wtl[(size_t)3072*1024];
__device__ __nv_bfloat16 g_R2h[(size_t)1024*1024];
__device__ __nv_bfloat16 g_R2l[(size_t)1024*1024];
__device__ __nv_bfloat16 g_RWth[(size_t)1024*1024];
__device__ __nv_bfloat16 g_RWtl[(size_t)1024*1024];
__device__ __nv_bfloat16 g_OWth[(size_t)1024*1024];
__device__ __nv_bfloat16 g_OWtl[(size_t)1024*1024];
__device__ __nv_bfloat16 g_AVh[(size_t)8192*1024];
__device__ __nv_bfloat16 g_AVl[(size_t)8192*1024];

// ---------------- attention bf16 operands ----------------
__device__ __nv_bfloat16 g_Qrwh[(size_t)BSZ*NH*QLEN*DH];  // (Q+rw_bias) hi
__device__ __nv_bfloat16 g_Qrwl[(size_t)BSZ*NH*QLEN*DH];
__device__ __nv_bfloat16 g_Qrrh[(size_t)BSZ*NH*QLEN*DH];  // (Q+rr_bias) hi
__device__ __nv_bfloat16 g_Qrrl[(size_t)BSZ*NH*QLEN*DH];
__device__ __nv_bfloat16 g_Khb [(size_t)BSZ*NH*KLEN*DH];
__device__ __nv_bfloat16 g_Klb [(size_t)BSZ*NH*KLEN*DH];
__device__ __nv_bfloat16 g_Vth [(size_t)BSZ*NH*DH*KLEN];  // V^T per head [d][j]
__device__ __nv_bfloat16 g_Vtl [(size_t)BSZ*NH*DH*KLEN];
__device__ __nv_bfloat16 g_Rkh [(size_t)NH*KLEN*DH];
__device__ __nv_bfloat16 g_Rkl [(size_t)NH*KLEN*DH];

// ================= helpers =================
__device__ __forceinline__ uint32_t smem_u32(const void* p) {
    uint32_t a;
    asm("{ .reg .u64 t; cvta.to.shared.u64 t, %1; cvt.u32.u64 %0, t; }" : "=r"(a) : "l"(p));
    return a;
}
__device__ __forceinline__ void ldsm4(uint32_t a[4], uint32_t addr) {
    asm volatile("ldmatrix.sync.aligned.m8n8.x4.shared.b16 {%0,%1,%2,%3}, [%4];"
                 : "=r"(a[0]), "=r"(a[1]), "=r"(a[2]), "=r"(a[3]) : "r"(addr));
}
__device__ __forceinline__ void ldsm2(uint32_t b[2], uint32_t addr) {
    asm volatile("ldmatrix.sync.aligned.m8n8.x2.shared.b16 {%0,%1}, [%2];"
                 : "=r"(b[0]), "=r"(b[1]) : "r"(addr));
}
__device__ __forceinline__ void mma16816(float c[4], const uint32_t a[4], const uint32_t b[2]) {
    asm volatile("mma.sync.aligned.m16n8k16.row.col.f32.bf16.bf16.f32 "
        "{%0,%1,%2,%3}, {%4,%5,%6,%7}, {%8,%9}, {%0,%1,%2,%3};"
        : "+f"(c[0]), "+f"(c[1]), "+f"(c[2]), "+f"(c[3])
        : "r"(a[0]), "r"(a[1]), "r"(a[2]), "r"(a[3]), "r"(b[0]), "r"(b[1]));
}
__device__ __forceinline__ void cpa16(uint32_t dst, const void* src) {
    asm volatile("cp.async.cg.shared.global [%0], [%1], 16;" :: "r"(dst), "l"(src));
}
#define CPA_COMMIT() asm volatile("cp.async.commit_group;")
#define CPA_WAIT1()  asm volatile("cp.async.wait_group 1;")

__device__ __forceinline__ void split1(float v, __nv_bfloat16& hi, __nv_bfloat16& lo) {
    hi = __float2bfloat16(v);
    lo = __float2bfloat16(v - __bfloat162float(hi));
}
__device__ __forceinline__ uint32_t f2bf2(float a, float b) {
    __nv_bfloat162 t = __floats2bfloat162_rn(a, b);
    return *reinterpret_cast<uint32_t*>(&t);
}
__device__ __forceinline__ uint32_t sphys(int r, int ch) {   // 128B rows, XOR swizzle
    return (uint32_t)(r * 128 + ((ch ^ (r & 7)) << 4));
}

// ---------------- split kernels ----------------
__global__ __launch_bounds__(256) void split_k(
    const float* __restrict__ src, __nv_bfloat16* __restrict__ h,
    __nv_bfloat16* __restrict__ l, int n4)
{
    int i = blockIdx.x * 256 + threadIdx.x;
    if (i >= n4) return;
    float4 v = ((const float4*)src)[i];
    __nv_bfloat16 hh[4], ll[4];
    split1(v.x, hh[0], ll[0]); split1(v.y, hh[1], ll[1]);
    split1(v.z, hh[2], ll[2]); split1(v.w, hh[3], ll[3]);
    ((uint2*)h)[i] = *(uint2*)hh;
    ((uint2*)l)[i] = *(uint2*)ll;
}

__global__ __launch_bounds__(256) void tsplit_k(
    const float* __restrict__ src, __nv_bfloat16* __restrict__ th,
    __nv_bfloat16* __restrict__ tl, int K, int N)
{
    __shared__ float tile[32][33];
    const int n0 = blockIdx.x * 32, k0 = blockIdx.y * 32;
    const int tx = threadIdx.x & 31, ty0 = threadIdx.x >> 5;
#pragma unroll
    for (int it = 0; it < 4; ++it) {
        int ty = ty0 + it * 8;
        tile[ty][tx] = src[(size_t)(k0 + ty) * N + n0 + tx];
    }
    __syncthreads();
#pragma unroll
    for (int it = 0; it < 4; ++it) {
        int ty = ty0 + it * 8;
        float v = tile[tx][ty];
        __nv_bfloat16 hi, lo; split1(v, hi, lo);
        th[(size_t)(n0 + ty) * K + k0 + tx] = hi;
        tl[(size_t)(n0 + ty) * K + k0 + tx] = lo;
    }
}

// Q + biases -> split   (one thread per float2)
__global__ __launch_bounds__(256) void qsplit_k(
    const float* __restrict__ rwb, const float* __restrict__ rrb)
{
    size_t e = (size_t)blockIdx.x * 256 + threadIdx.x;     // 4,194,304 units
    float2 q = ((const float2*)g_Q)[e];
    int d = (int)((e * 2) & 63);
    int n = (int)(((e * 2) >> 15) & 15);
    float b0 = rwb[n*64 + d], b1 = rwb[n*64 + d + 1];
    __nv_bfloat16 h0, l0, h1, l1;
    split1(q.x + b0, h0, l0); split1(q.y + b1, h1, l1);
    ((uint32_t*)g_Qrwh)[e] = ((uint32_t)*(uint16_t*)&h1 << 16) | *(uint16_t*)&h0;
    ((uint32_t*)g_Qrwl)[e] = ((uint32_t)*(uint16_t*)&l1 << 16) | *(uint16_t*)&l0;
    float c0 = rrb[n*64 + d], c1 = rrb[n*64 + d + 1];
    split1(q.x + c0, h0, l0); split1(q.y + c1, h1, l1);
    ((uint32_t*)g_Qrrh)[e] = ((uint32_t)*(uint16_t*)&h1 << 16) | *(uint16_t*)&h0;
    ((uint32_t*)g_Qrrl)[e] = ((uint32_t)*(uint16_t*)&l1 << 16) | *(uint16_t*)&l0;
}

// per-head V transpose + split: g_V [bn][j][d] -> g_Vt [bn][d][j]
__global__ __launch_bounds__(256) void vtrans_k()
{
    __shared__ float tile[64][65];
    const int j0 = blockIdx.x * 64;
    const int bn = blockIdx.y;
    const int tid = threadIdx.x;
#pragma unroll
    for (int it = 0; it < 16; ++it) {
        int idx = tid + it * 256;
        int j = idx >> 6, d = idx & 63;
        tile[j][d] = g_V[((size_t)bn * 1024 + j0 + j) * 64 + d];
    }
    __syncthreads();
#pragma unroll
    for (int it = 0; it < 16; ++it) {
        int idx = tid + it * 256;
        int d = idx >> 6, j = idx & 63;
        __nv_bfloat16 hi, lo; split1(tile[j][d], hi, lo);
        g_Vth[((size_t)bn * 64 + d) * 1024 + j0 + j] = hi;
        g_Vtl[((size_t)bn * 64 + d) * 1024 + j0 + j] = lo;
    }
}

// ---------------- split-bf16 HMMA GEMM (unchanged from R5) ----------------
#define GSTG 65536
#define GTC_SMEM (2*GSTG)

template<int MODE>
__global__ __launch_bounds__(256, 1) void gemm_bf(
    const __nv_bfloat16* __restrict__ Ah, const __nv_bfloat16* __restrict__ Al,
    const __nv_bfloat16* __restrict__ Bh, const __nv_bfloat16* __restrict__ Bl,
    float* __restrict__ C)
{
    const int m0 = blockIdx.y * 128;
    const int n0 = blockIdx.x * 128;
    if (MODE == 0 && n0 < 1024 && m0 < 8192) return;

    extern __shared__ char sm[];
    const int tid  = threadIdx.x;
    const int wid  = tid >> 5;
    const int lane = tid & 31;
    const int wm   = wid >> 2;
    const int wn   = wid & 3;
    const uint32_t smb = smem_u32(sm);

    float acc[4][4][4];
#pragma unroll
    for (int i = 0; i < 4; i++)
#pragma unroll
        for (int j = 0; j < 4; j++)
#pragma unroll
            for (int q = 0; q < 4; q++) acc[i][j][q] = 0.f;

    const int lr = tid >> 3;
    const int lc = tid & 7;

    auto load_stage = [&](int c, int stg) {
        const int k0 = c * 64;
        const uint32_t base = smb + stg * GSTG;
#pragma unroll
        for (int it = 0; it < 4; ++it) {
            int r = lr + it * 32;
            uint32_t dst = base + (uint32_t)(r * 128 + ((lc ^ (r & 7)) << 4));
            const size_t aoff = (size_t)(m0 + r) * 1024 + k0 + lc * 8;
            const size_t boff = (size_t)(n0 + r) * 1024 + k0 + lc * 8;
            cpa16(dst,          Ah + aoff);
            cpa16(dst + 16384,  Al + aoff);
            cpa16(dst + 32768,  Bh + boff);
            cpa16(dst + 49152,  Bl + boff);
        }
        CPA_COMMIT();
    };

    auto compute = [&](int stg) {
        const uint32_t base = smb + stg * GSTG;
#pragma unroll
        for (int s = 0; s < 4; ++s) {
            uint32_t ahi[4][4], alo[4][4], bhi[4][2], blo[4][2];
#pragma unroll
            for (int i = 0; i < 4; ++i) {
                int row = wm * 64 + i * 16 + (lane & 15);
                int ch  = s * 2 + (lane >> 4);
                uint32_t addr = base + (uint32_t)(row * 128 + ((ch ^ (row & 7)) << 4));
                ldsm4(ahi[i], addr);
                ldsm4(alo[i], addr + 16384);
            }
#pragma unroll
            for (int j = 0; j < 4; ++j) {
                int row = wn * 32 + j * 8 + (lane & 7);
                int ch  = s * 2 + ((lane >> 3) & 1);
                uint32_t addr = base + 32768u + (uint32_t)(row * 128 + ((ch ^ (row & 7)) << 4));
                ldsm2(bhi[j], addr);
                ldsm2(blo[j], addr + 16384);
            }
#pragma unroll
            for (int i = 0; i < 4; ++i)
#pragma unroll
                for (int j = 0; j < 4; ++j) {
                    mma16816(acc[i][j], ahi[i], bhi[j]);
                    mma16816(acc[i][j], ahi[i], blo[j]);
                    mma16816(acc[i][j], alo[i], bhi[j]);
                }
        }
    };

    load_stage(0, 0);
    load_stage(1, 1);
#pragma unroll 1
    for (int c = 0; c < 16; ++c) {
        CPA_WAIT1();
        __syncthreads();
        compute(c & 1);
        __syncthreads();
        if (c + 2 < 16) load_stage(c + 2, c & 1);
        else            CPA_COMMIT();
    }

    const int g   = lane >> 2;
    const int tig = lane & 3;

    auto storeC = [&](int m, int col, float v0, float v1) {
        if (MODE == 0) {
            int kl = m >> 4, bb = m & 15;
            int sec = col >> 10, hn = (col >> 6) & 15, d = col & 63;
            float2 v = make_float2(v0, v1);
            if (sec == 0) {
                if (kl >= MLEN)
                    *(float2*)&g_Q[((size_t)(bb*NH+hn)*QLEN + (kl-MLEN))*DH + d] = v;
            } else if (sec == 1) {
                *(float2*)&g_K[((size_t)(bb*NH+hn)*KLEN + kl)*DH + d] = v;
            } else {
                *(float2*)&g_V[((size_t)(bb*NH+hn)*KLEN + kl)*DH + d] = v;
            }
        } else if (MODE == 1) {
            int hn = col >> 6, d = col & 63;
            *(float2*)&g_Rk[((size_t)hn*KLEN + m)*DH + d] = make_float2(v0, v1);
        } else {
            *(float2*)&C[(size_t)m * 1024 + col] = make_float2(v0, v1);
        }
    };

#pragma unroll
    for (int i = 0; i < 4; ++i)
#pragma unroll
        for (int j = 0; j < 4; ++j) {
            int m   = m0 + wm*64 + i*16 + g;
            int col = n0 + wn*32 + j*8 + 2*tig;
            storeC(m,     col, acc[i][j][0], acc[i][j][1]);
            storeC(m + 8, col, acc[i][j][2], acc[i][j][3]);
        }
}

// ---------------- BD via HMMA: BD[i][u] = (q+rrb)·rk, 3-split ----------------
// block: (i-tile 64) x (bn). 128 thr, warp = 16 rows.
// smem: Qh 8K | Ql 8K | stage s: Rkh 8K | Rkl 8K   (16K + 2*16K = 48K)
#define BD_SMEM 49152
__global__ __launch_bounds__(128, 2) void bd_mma()
{
    extern __shared__ char sm[];
    const int i0 = blockIdx.x * 64;
    const int bn = blockIdx.y;
    const int nh = bn & 15;
    const int tid = threadIdx.x, wid = tid >> 5, lane = tid & 31;
    const uint32_t smb = smem_u32(sm);

    const int us = (448 - i0) > 0 ? (448 - i0) : 0;
    const int nt = (1024 - us) >> 6;

    const __nv_bfloat16* Qh = g_Qrrh + ((size_t)bn*512 + i0) * 64;
    const __nv_bfloat16* Ql = g_Qrrl + ((size_t)bn*512 + i0) * 64;

    // Q load (two 8KB arrays)
#pragma unroll
    for (int it = 0; it < 4; ++it) {
        int idx = tid + it * 128;
        int r = idx >> 3, ch = idx & 7;
        cpa16(smb + sphys(r, ch),        Qh + r*64 + ch*8);
        cpa16(smb + 8192 + sphys(r, ch), Ql + r*64 + ch*8);
    }
    CPA_COMMIT();

    auto load_rk = [&](int t) {
        if (t < nt) {
            int u0 = us + t * 64;
            uint32_t base = smb + 16384 + (t & 1) * 16384;
#pragma unroll
            for (int it = 0; it < 4; ++it) {
                int idx = tid + it * 128;
                int r = idx >> 3, ch = idx & 7;
                cpa16(base + sphys(r, ch),        g_Rkh + ((size_t)nh*1024 + u0 + r)*64 + ch*8);
                cpa16(base + 8192 + sphys(r, ch), g_Rkl + ((size_t)nh*1024 + u0 + r)*64 + ch*8);
            }
        }
        CPA_COMMIT();
    };
    load_rk(0);
    load_rk(1);

    uint32_t aqh[4][4], aql[4][4];
    bool afrag = false;

    const int g = lane >> 2, tig = lane & 3;
    const int r0 = i0 + wid * 16 + g;

#pragma unroll 1
    for (int t = 0; t < nt; ++t) {
        CPA_WAIT1();
        __syncthreads();
        if (!afrag) {
            afrag = true;
#pragma unroll
            for (int kc = 0; kc < 4; ++kc) {
                int row = wid * 16 + (lane & 15);
                int ch  = kc * 2 + (lane >> 4);
                ldsm4(aqh[kc], smb + sphys(row, ch));
                ldsm4(aql[kc], smb + 8192 + sphys(row, ch));
            }
        }
        const uint32_t base = smb + 16384 + (t & 1) * 16384;
        const int u0 = us + t * 64;
        float* bd0 = g_BD + ((size_t)bn*512 + r0) * 1024 + u0;
        float* bd1 = bd0 + 8 * 1024;

#pragma unroll
        for (int jt = 0; jt < 8; ++jt) {
            float sa[4] = {0.f, 0.f, 0.f, 0.f};
            uint32_t kh[4][2], kl2[4][2], tmp[4];
#pragma unroll
            for (int kp = 0; kp < 2; ++kp) {
                int row = jt * 8 + (lane & 7);
                int ch  = kp * 4 + (lane >> 3);
                ldsm4(tmp, base + sphys(row, ch));
                kh[kp*2][0] = tmp[0]; kh[kp*2][1] = tmp[1];
                kh[kp*2+1][0] = tmp[2]; kh[kp*2+1][1] = tmp[3];
                ldsm4(tmp, base + 8192 + sphys(row, ch));
                kl2[kp*2][0] = tmp[0]; kl2[kp*2][1] = tmp[1];
                kl2[kp*2+1][0] = tmp[2]; kl2[kp*2+1][1] = tmp[3];
            }
#pragma unroll
            for (int kc = 0; kc < 4; ++kc) {
                mma16816(sa, aqh[kc], kh[kc]);
                mma16816(sa, aqh[kc], kl2[kc]);
                mma16816(sa, aql[kc], kh[kc]);
            }
            int uc = jt * 8 + 2 * tig;
            *(float2*)(bd0 + uc) = make_float2(sa[0], sa[1]);
            *(float2*)(bd1 + uc) = make_float2(sa[2], sa[3]);
        }
        __syncthreads();
        load_rk(t + 2);
    }
}

// ---------------- fused attention via HMMA + online softmax ----------------
// block: (i-tile 64) x (bn). 128 thr, warp = 16 rows.
// smem: Qh 8K | Ql 8K | stage s (2x): Kh 8K | Kl 8K | Vh 8K | Vl 8K  => 80K
#define ATT_SMEM 81920
__global__ __launch_bounds__(128, 2) void attn_mma()
{
    extern __shared__ char sm[];
    const int i0 = blockIdx.x * 64;
    const int bn = blockIdx.y;
    const int b = bn >> 4, nh = bn & 15;
    const int tid = threadIdx.x, wid = tid >> 5, lane = tid & 31;
    const uint32_t smb = smem_u32(sm);

    const int nt = (i0 >> 6) + 9;

    const __nv_bfloat16* Qh = g_Qrwh + ((size_t)bn*512 + i0) * 64;
    const __nv_bfloat16* Ql = g_Qrwl + ((size_t)bn*512 + i0) * 64;

#pragma unroll
    for (int it = 0; it < 4; ++it) {
        int idx = tid + it * 128;
        int r = idx >> 3, ch = idx & 7;
        cpa16(smb + sphys(r, ch),        Qh + r*64 + ch*8);
        cpa16(smb + 8192 + sphys(r, ch), Ql + r*64 + ch*8);
    }

    auto load_kv = [&](int t) {
        if (t < nt) {
            int j0 = t * 64;
            uint32_t base = smb + 16384 + (t & 1) * 32768;
#pragma unroll
            for (int it = 0; it < 4; ++it) {
                int idx = tid + it * 128;
                int r = idx >> 3, ch = idx & 7;
                size_t ko = ((size_t)bn*1024 + j0 + r) * 64 + ch*8;
                size_t vo = ((size_t)bn*64 + r) * 1024 + j0 + ch*8;
                cpa16(base + sphys(r, ch),         g_Khb + ko);
                cpa16(base + 8192  + sphys(r, ch), g_Klb + ko);
                cpa16(base + 16384 + sphys(r, ch), g_Vth + vo);
                cpa16(base + 24576 + sphys(r, ch), g_Vtl + vo);
            }
        }
        CPA_COMMIT();
    };
    load_kv(0);   // commits Q + KV0 together
    load_kv(1);

    uint32_t aqh[4][4], aql[4][4];
    bool afrag = false;

    const int g = lane >> 2, tig = lane & 3;
    const int r0 = i0 + wid * 16 + g;
    const int r1 = r0 + 8;
    const float* bd0 = g_BD + ((size_t)bn*512 + r0) * 1024;
    const float* bd1 = bd0 + 8 * 1024;

    float mi0 = -1e30f, mi1 = -1e30f, li0 = 0.f, li1 = 0.f;
    float oacc[8][4];
#pragma unroll
    for (int dt = 0; dt < 8; ++dt)
#pragma unroll
        for (int q = 0; q < 4; ++q) oacc[dt][q] = 0.f;

#pragma unroll 1
    for (int t = 0; t < nt; ++t) {
        CPA_WAIT1();
        __syncthreads();
        if (!afrag) {
            afrag = true;
#pragma unroll
            for (int kc = 0; kc < 4; ++kc) {
                int row = wid * 16 + (lane & 15);
                int ch  = kc * 2 + (lane >> 4);
                ldsm4(aqh[kc], smb + sphys(row, ch));
                ldsm4(aql[kc], smb + 8192 + sphys(row, ch));
            }
        }
        const uint32_t kbase = smb + 16384 + (t & 1) * 32768;
        const int j0 = t * 64;

        // ---- S = Q·K^T (3-split) ----
        float sa[8][4];
#pragma unroll
        for (int jt = 0; jt < 8; ++jt) {
            sa[jt][0] = sa[jt][1] = sa[jt][2] = sa[jt][3] = 0.f;
            uint32_t kh[4][2], kl2[4][2], tmp[4];
#pragma unroll
            for (int kp = 0; kp < 2; ++kp) {
                int row = jt * 8 + (lane & 7);
                int ch  = kp * 4 + (lane >> 3);
                ldsm4(tmp, kbase + sphys(row, ch));
                kh[kp*2][0] = tmp[0]; kh[kp*2][1] = tmp[1];
                kh[kp*2+1][0] = tmp[2]; kh[kp*2+1][1] = tmp[3];
                ldsm4(tmp, kbase + 8192 + sphys(row, ch));
                kl2[kp*2][0] = tmp[0]; kl2[kp*2][1] = tmp[1];
                kl2[kp*2+1][0] = tmp[2]; kl2[kp*2+1][1] = tmp[3];
            }
#pragma unroll
            for (int kc = 0; kc < 4; ++kc) {
                mma16816(sa[jt], aqh[kc], kh[kc]);
                mma16816(sa[jt], aqh[kc], kl2[kc]);
                mma16816(sa[jt], aql[kc], kh[kc]);
            }
        }

        // ---- + BD, scale, mask ----
#pragma unroll
        for (int jt = 0; jt < 8; ++jt) {
            int j = j0 + jt * 8 + 2 * tig;
            sa[jt][0] = (j     <= r0 + 512) ? (sa[jt][0] + bd0[j + 511 - r0]) * 0.125f : -1e30f;
            sa[jt][1] = (j + 1 <= r0 + 512) ? (sa[jt][1] + bd0[j + 512 - r0]) * 0.125f : -1e30f;
            sa[jt][2] = (j     <= r1 + 512) ? (sa[jt][2] + bd1[j + 511 - r1]) * 0.125f : -1e30f;
            sa[jt][3] = (j + 1 <= r1 + 512) ? (sa[jt][3] + bd1[j + 512 - r1]) * 0.125f : -1e30f;
        }

        // ---- online softmax ----
        float m0 = -1e30f, m1 = -1e30f;
#pragma unroll
        for (int jt = 0; jt < 8; ++jt) {
            m0 = fmaxf(m0, fmaxf(sa[jt][0], sa[jt][1]));
            m1 = fmaxf(m1, fmaxf(sa[jt][2], sa[jt][3]));
        }
        m0 = fmaxf(m0, __shfl_xor_sync(0xffffffffu, m0, 1));
        m0 = fmaxf(m0, __shfl_xor_sync(0xffffffffu, m0, 2));
        m1 = fmaxf(m1, __shfl_xor_sync(0xffffffffu, m1, 1));
        m1 = fmaxf(m1, __shfl_xor_sync(0xffffffffu, m1, 2));
        float mn0 = fmaxf(mi0, m0), mn1 = fmaxf(mi1, m1);
        float al0 = __expf(mi0 - mn0), al1 = __expf(mi1 - mn1);
        mi0 = mn0; mi1 = mn1;
        float s0 = 0.f, s1 = 0.f;
#pragma unroll
        for (int jt = 0; jt < 8; ++jt) {
            sa[jt][0] = __expf(sa[jt][0] - mn0); s0 += sa[jt][0];
            sa[jt][1] = __expf(sa[jt][1] - mn0); s0 += sa[jt][1];
            sa[jt][2] = __expf(sa[jt][2] - mn1); s1 += sa[jt][2];
            sa[jt][3] = __expf(sa[jt][3] - mn1); s1 += sa[jt][3];
        }
        s0 += __shfl_xor_sync(0xffffffffu, s0, 1);
        s0 += __shfl_xor_sync(0xffffffffu, s0, 2);
        s1 += __shfl_xor_sync(0xffffffffu, s1, 1);
        s1 += __shfl_xor_sync(0xffffffffu, s1, 2);
        li0 = li0 * al0 + s0;
        li1 = li1 * al1 + s1;
#pragma unroll
        for (int dt = 0; dt < 8; ++dt) {
            oacc[dt][0] *= al0; oacc[dt][1] *= al0;
            oacc[dt][2] *= al1; oacc[dt][3] *= al1;
        }

        // ---- pack P (register repack C-frag -> A-frag) ----
        uint32_t pf[4][4];
#pragma unroll
        for (int kc = 0; kc < 4; ++kc) {
            pf[kc][0] = f2bf2(sa[2*kc][0],   sa[2*kc][1]);
            pf[kc][1] = f2bf2(sa[2*kc][2],   sa[2*kc][3]);
            pf[kc][2] = f2bf2(sa[2*kc+1][0], sa[2*kc+1][1]);
            pf[kc][3] = f2bf2(sa[2*kc+1][2], sa[2*kc+1][3]);
        }

        // ---- O += P · V (V split hi/lo) ----
        const uint32_t vbase = kbase + 16384;
#pragma unroll
        for (int dt = 0; dt < 8; ++dt) {
            uint32_t vh[4][2], vl[4][2], tmp[4];
#pragma unroll
            for (int kp = 0; kp < 2; ++kp) {
                int row = dt * 8 + (lane & 7);
                int ch  = kp * 4 + (lane >> 3);
                ldsm4(tmp, vbase + sphys(row, ch));
                vh[kp*2][0] = tmp[0]; vh[kp*2][1] = tmp[1];
                vh[kp*2+1][0] = tmp[2]; vh[kp*2+1][1] = tmp[3];
                ldsm4(tmp, vbase + 8192 + sphys(row, ch));
                vl[kp*2][0] = tmp[0]; vl[kp*2][1] = tmp[1];
                vl[kp*2+1][0] = tmp[2]; vl[kp*2+1][1] = tmp[3];
            }
#pragma unroll
            for (int kc = 0; kc < 4; ++kc) {
                mma16816(oacc[dt], pf[kc], vh[kc]);
                mma16816(oacc[dt], pf[kc], vl[kc]);
            }
        }
        __syncthreads();
        load_kv(t + 2);
    }

    float inv0 = 1.f / li0, inv1 = 1.f / li1;
#pragma unroll
    for (int dt = 0; dt < 8; ++dt) {
        int d = nh * 64 + dt * 8 + 2 * tig;
        *(float2*)&g_AV[((size_t)r0 * 16 + b) * 1024 + d] =
            make_float2(oacc[dt][0] * inv0, oacc[dt][1] * inv0);
        *(float2*)&g_AV[((size_t)r1 * 16 + b) * 1024 + d] =
            make_float2(oacc[dt][2] * inv1, oacc[dt][3] * inv1);
    }
}

// ---------------- residual + layernorm ----------------
__global__ __launch_bounds__(256) void ln_kernel(
    const float* __restrict__ w, const float* __restrict__ gamma,
    const float* __restrict__ beta, float* __restrict__ out)
{
    const int row = blockIdx.x;
    const int tid = threadIdx.x;
    __shared__ float red[256];
    const float* wrow = w   + (size_t)row * 1024;
    float*       orow = out + (size_t)row * 1024;

    float x[4];
    float sum = 0.f;
#pragma unroll
    for (int l = 0; l < 4; l++) {
        int c = tid + l*256;
        x[l] = wrow[c] + orow[c];
        sum += x[l];
    }
    red[tid] = sum; __syncthreads();
    for (int s = 128; s > 0; s >>= 1) {
        if (tid < s) red[tid] += red[tid + s];
        __syncthreads();
    }
    float mu = red[0] * (1.f/1024.f);
    __syncthreads();

    float vs = 0.f;
#pragma unroll
    for (int l = 0; l < 4; l++) { float dx = x[l] - mu; vs += dx*dx; }
    red[tid] = vs; __syncthreads();
    for (int s = 128; s > 0; s >>= 1) {
        if (tid < s) red[tid] += red[tid + s];
        __syncthreads();
    }
    float rstd = rsqrtf(red[0] * (1.f/1024.f) + 1e-6f);

#pragma unroll
    for (int l = 0; l < 4; l++) {
        int c = tid + l*256;
        orow[c] = (x[l] - mu) * rstd * gamma[c] + beta[c];
    }
}

// ---------------- launch ----------------
extern "C" void kernel_launch(void* const* d_in, const int* in_sizes, int n_in,
                              void* d_out, int out_size)
{
    const float* w      = (const float*)d_in[0];
    const float* r      = (const float*)d_in[1];
    const float* mems   = (const float*)d_in[3];
    const float* qkvw   = (const float*)d_in[4];
    const float* rw     = (const float*)d_in[5];
    const float* ow     = (const float*)d_in[6];
    const float* rrb    = (const float*)d_in[7];
    const float* rwbias = (const float*)d_in[8];
    const float* gamma  = (const float*)d_in[9];
    const float* beta   = (const float*)d_in[10];
    float* out = (float*)d_out;

    __nv_bfloat16 *Ah, *Al, *Wth, *Wtl, *R2h, *R2l, *RWth, *RWtl, *OWth, *OWtl, *AVh, *AVl;
    __nv_bfloat16 *Rkh_p, *Rkl_p;
    float *AV, *Rk_p;
    cudaGetSymbolAddress((void**)&Ah,  g_Ah);  cudaGetSymbolAddress((void**)&Al,  g_Al);
    cudaGetSymbolAddress((void**)&Wth, g_Wth); cudaGetSymbolAddress((void**)&Wtl, g_Wtl);
    cudaGetSymbolAddress((void**)&R2h, g_R2h); cudaGetSymbolAddress((void**)&R2l, g_R2l);
    cudaGetSymbolAddress((void**)&RWth,g_RWth);cudaGetSymbolAddress((void**)&RWtl,g_RWtl);
    cudaGetSymbolAddress((void**)&OWth,g_OWth);cudaGetSymbolAddress((void**)&OWtl,g_OWtl);
    cudaGetSymbolAddress((void**)&AVh, g_AVh); cudaGetSymbolAddress((void**)&AVl, g_AVl);
    cudaGetSymbolAddress((void**)&AV,  g_AV);
    cudaGetSymbolAddress((void**)&Rkh_p, g_Rkh); cudaGetSymbolAddress((void**)&Rkl_p, g_Rkl);
    cudaGetSymbolAddress((void**)&Rk_p,  g_Rk);
    float* K_p; cudaGetSymbolAddress((void**)&K_p, g_K);
    __nv_bfloat16 *Khb_p, *Klb_p;
    cudaGetSymbolAddress((void**)&Khb_p, g_Khb); cudaGetSymbolAddress((void**)&Klb_p, g_Klb);

    cudaFuncSetAttribute(gemm_bf<0>, cudaFuncAttributeMaxDynamicSharedMemorySize, GTC_SMEM);
    cudaFuncSetAttribute(gemm_bf<1>, cudaFuncAttributeMaxDynamicSharedMemorySize, GTC_SMEM);
    cudaFuncSetAttribute(gemm_bf<2>, cudaFuncAttributeMaxDynamicSharedMemorySize, GTC_SMEM);
    cudaFuncSetAttribute(bd_mma,   cudaFuncAttributeMaxDynamicSharedMemorySize, BD_SMEM);
    cudaFuncSetAttribute(attn_mma, cudaFuncAttributeMaxDynamicSharedMemorySize, ATT_SMEM);

    // pre-split GEMM inputs
    split_k <<<8192, 256>>>(mems, Ah, Al, 2097152);
    split_k <<<8192, 256>>>(w, Ah + (size_t)8192*1024, Al + (size_t)8192*1024, 2097152);
    tsplit_k<<<dim3(96, 32), 256>>>(qkvw, Wth, Wtl, 1024, 3072);
    split_k <<<1024, 256>>>(r, R2h, R2l, 262144);
    tsplit_k<<<dim3(32, 32), 256>>>(rw, RWth, RWtl, 1024, 1024);
    tsplit_k<<<dim3(32, 32), 256>>>(ow, OWth, OWtl, 1024, 1024);

    // big GEMMs
    gemm_bf<0><<<dim3(24, 128), 256, GTC_SMEM>>>(Ah, Al, Wth, Wtl, nullptr);
    gemm_bf<1><<<dim3(8, 8),    256, GTC_SMEM>>>(R2h, R2l, RWth, RWtl, nullptr);

    // attention operand prep
    qsplit_k<<<16384, 256>>>(rwbias, rrb);
    split_k <<<32768, 256>>>(K_p, Khb_p, Klb_p, 4194304);
    vtrans_k<<<dim3(16, 256), 256>>>();
    split_k <<<2048, 256>>>(Rk_p, Rkh_p, Rkl_p, 262144);

    // BD + attention
    bd_mma  <<<dim3(8, 256), 128, BD_SMEM>>>();
    attn_mma<<<dim3(8, 256), 128, ATT_SMEM>>>();

    // output projection + layernorm
    split_k <<<8192, 256>>>(AV, AVh, AVl, 2097152);
    gemm_bf<2><<<dim3(8, 64),   256, GTC_SMEM>>>(AVh, AVl, OWth, OWtl, out);
    ln_kernel  <<<8192, 256>>>(w, gamma, beta, out);
}

// round 8
// speedup vs baseline: 4.2357x; 1.3661x over previous
// Resubmission of Round-7 kernel (R7 bench died with an infra-level
// "container failed twice"; kernel audit found no container-killing defect).
#include <cuda_runtime.h>
#include <cuda_fp16.h>
#include <math.h>
#include <stdint.h>

#define QLEN 512
#define MLEN 512
#define KLEN 1024
#define BSZ  16
#define NH   16
#define DH   64
#define DM   1024
#define HID  1024

// ---------------- scratch ----------------
__device__ float  g_V  [(size_t)BSZ*NH*KLEN*DH];          // fp32 V (for transpose)
__device__ __half g_BDh[(size_t)BSZ*NH*QLEN*KLEN];        // BD scores fp16

__device__ __half g_Ah [(size_t)16384*1024];              // cat(mems,w) split
__device__ __half g_Al [(size_t)16384*1024];
__device__ __half g_Wth[(size_t)3072*1024];               // qkv_w^T single
__device__ __half g_R2h[(size_t)1024*1024];               // r split
__device__ __half g_R2l[(size_t)1024*1024];
__device__ __half g_RWth[(size_t)1024*1024];              // r_w^T single
__device__ __half g_OWth[(size_t)1024*1024];              // o_w^T single
__device__ __half g_AVh[(size_t)8192*1024];               // attn_vec split
__device__ __half g_AVl[(size_t)8192*1024];

__device__ __half g_Qrwh[(size_t)BSZ*NH*QLEN*DH];         // (Q+rw_bias) split
__device__ __half g_Qrwl[(size_t)BSZ*NH*QLEN*DH];
__device__ __half g_Qrrh[(size_t)BSZ*NH*QLEN*DH];         // (Q+rr_bias) split
__device__ __half g_Qrrl[(size_t)BSZ*NH*QLEN*DH];
__device__ __half g_Khb [(size_t)BSZ*NH*KLEN*DH];         // K single
__device__ __half g_Vth [(size_t)BSZ*NH*DH*KLEN];         // V^T single
__device__ __half g_Rkh [(size_t)NH*KLEN*DH];             // Rk single

// ================= helpers =================
__device__ __forceinline__ uint32_t smem_u32(const void* p) {
    uint32_t a;
    asm("{ .reg .u64 t; cvta.to.shared.u64 t, %1; cvt.u32.u64 %0, t; }" : "=r"(a) : "l"(p));
    return a;
}
__device__ __forceinline__ void ldsm4(uint32_t a[4], uint32_t addr) {
    asm volatile("ldmatrix.sync.aligned.m8n8.x4.shared.b16 {%0,%1,%2,%3}, [%4];"
                 : "=r"(a[0]), "=r"(a[1]), "=r"(a[2]), "=r"(a[3]) : "r"(addr));
}
__device__ __forceinline__ void ldsm2(uint32_t b[2], uint32_t addr) {
    asm volatile("ldmatrix.sync.aligned.m8n8.x2.shared.b16 {%0,%1}, [%2];"
                 : "=r"(b[0]), "=r"(b[1]) : "r"(addr));
}
__device__ __forceinline__ void mma16816(float c[4], const uint32_t a[4], const uint32_t b[2]) {
    asm volatile("mma.sync.aligned.m16n8k16.row.col.f32.f16.f16.f32 "
        "{%0,%1,%2,%3}, {%4,%5,%6,%7}, {%8,%9}, {%0,%1,%2,%3};"
        : "+f"(c[0]), "+f"(c[1]), "+f"(c[2]), "+f"(c[3])
        : "r"(a[0]), "r"(a[1]), "r"(a[2]), "r"(a[3]), "r"(b[0]), "r"(b[1]));
}
__device__ __forceinline__ void cpa16(uint32_t dst, const void* src) {
    asm volatile("cp.async.cg.shared.global [%0], [%1], 16;" :: "r"(dst), "l"(src));
}
#define CPA_COMMIT() asm volatile("cp.async.commit_group;")
#define CPA_WAIT1()  asm volatile("cp.async.wait_group 1;")

__device__ __forceinline__ void split1h(float v, __half& hi, __half& lo) {
    hi = __float2half_rn(v);
    lo = __float2half_rn(v - __half2float(hi));
}
__device__ __forceinline__ uint32_t f2h2(float a, float b) {
    __half2 t = __floats2half2_rn(a, b);
    return *reinterpret_cast<uint32_t*>(&t);
}
__device__ __forceinline__ uint32_t sphys(int r, int ch) {   // 128B rows, XOR swizzle
    return (uint32_t)(r * 128 + ((ch ^ (r & 7)) << 4));
}

// ---------------- prep kernels ----------------
__global__ __launch_bounds__(256) void split_k(
    const float* __restrict__ src, __half* __restrict__ h,
    __half* __restrict__ l, int n4)
{
    int i = blockIdx.x * 256 + threadIdx.x;
    if (i >= n4) return;
    float4 v = ((const float4*)src)[i];
    __half hh[4], ll[4];
    split1h(v.x, hh[0], ll[0]); split1h(v.y, hh[1], ll[1]);
    split1h(v.z, hh[2], ll[2]); split1h(v.w, hh[3], ll[3]);
    ((uint2*)h)[i] = *(uint2*)hh;
    ((uint2*)l)[i] = *(uint2*)ll;
}

// transpose + round: src [K][N] fp32 -> th [N][K] fp16
__global__ __launch_bounds__(256) void tround_k(
    const float* __restrict__ src, __half* __restrict__ th, int K, int N)
{
    __shared__ float tile[32][33];
    const int n0 = blockIdx.x * 32, k0 = blockIdx.y * 32;
    const int tx = threadIdx.x & 31, ty0 = threadIdx.x >> 5;
#pragma unroll
    for (int it = 0; it < 4; ++it) {
        int ty = ty0 + it * 8;
        tile[ty][tx] = src[(size_t)(k0 + ty) * N + n0 + tx];
    }
    __syncthreads();
#pragma unroll
    for (int it = 0; it < 4; ++it) {
        int ty = ty0 + it * 8;
        th[(size_t)(n0 + ty) * K + k0 + tx] = __float2half_rn(tile[tx][ty]);
    }
}

// per-head V transpose: g_V [bn][j][d] fp32 -> g_Vth [bn][d][j] fp16
__global__ __launch_bounds__(256) void vtrans_k()
{
    __shared__ float tile[64][65];
    const int j0 = blockIdx.x * 64;
    const int bn = blockIdx.y;
    const int tid = threadIdx.x;
#pragma unroll
    for (int it = 0; it < 16; ++it) {
        int idx = tid + it * 256;
        int j = idx >> 6, d = idx & 63;
        tile[j][d] = g_V[((size_t)bn * 1024 + j0 + j) * 64 + d];
    }
    __syncthreads();
#pragma unroll
    for (int it = 0; it < 16; ++it) {
        int idx = tid + it * 256;
        int d = idx >> 6, j = idx & 63;
        g_Vth[((size_t)bn * 64 + d) * 1024 + j0 + j] = __float2half_rn(tile[j][d]);
    }
}

// ---------------- split-fp16 HMMA GEMM (2 MMAs), tile 128x128, BK=64 ----------------
// smem/stage 48K: Ah 16K | Al 16K | Bh 16K. 2 stages = 96K.
#define GSTG 49152
#define GTC_SMEM (2*GSTG)

template<int MODE>
__global__ __launch_bounds__(256, 1) void gemm_hf(
    const __half* __restrict__ Ah, const __half* __restrict__ Al,
    const __half* __restrict__ Bh, float* __restrict__ C,
    const float* __restrict__ rwb, const float* __restrict__ rrb)
{
    const int m0 = blockIdx.y * 128;
    const int n0 = blockIdx.x * 128;
    if (MODE == 0 && n0 < 1024 && m0 < 8192) return;   // Q of mems: dead

    extern __shared__ char sm[];
    const int tid  = threadIdx.x;
    const int wid  = tid >> 5;
    const int lane = tid & 31;
    const int wm   = wid >> 2;
    const int wn   = wid & 3;
    const uint32_t smb = smem_u32(sm);

    float acc[4][4][4];
#pragma unroll
    for (int i = 0; i < 4; i++)
#pragma unroll
        for (int j = 0; j < 4; j++)
#pragma unroll
            for (int q = 0; q < 4; q++) acc[i][j][q] = 0.f;

    const int lr = tid >> 3;
    const int lc = tid & 7;

    auto load_stage = [&](int c, int stg) {
        const int k0 = c * 64;
        const uint32_t base = smb + stg * GSTG;
#pragma unroll
        for (int it = 0; it < 4; ++it) {
            int r = lr + it * 32;
            uint32_t dst = base + sphys(r, lc);
            const size_t aoff = (size_t)(m0 + r) * 1024 + k0 + lc * 8;
            const size_t boff = (size_t)(n0 + r) * 1024 + k0 + lc * 8;
            cpa16(dst,          Ah + aoff);
            cpa16(dst + 16384,  Al + aoff);
            cpa16(dst + 32768,  Bh + boff);
        }
        CPA_COMMIT();
    };

    auto compute = [&](int stg) {
        const uint32_t base = smb + stg * GSTG;
#pragma unroll
        for (int s = 0; s < 4; ++s) {
            uint32_t ahi[4][4], alo[4][4], bh[4][2];
#pragma unroll
            for (int i = 0; i < 4; ++i) {
                int row = wm * 64 + i * 16 + (lane & 15);
                int ch  = s * 2 + (lane >> 4);
                uint32_t addr = base + sphys(row, ch);
                ldsm4(ahi[i], addr);
                ldsm4(alo[i], addr + 16384);
            }
#pragma unroll
            for (int j = 0; j < 4; ++j) {
                int row = wn * 32 + j * 8 + (lane & 7);
                int ch  = s * 2 + ((lane >> 3) & 1);
                ldsm2(bh[j], base + 32768u + sphys(row, ch));
            }
#pragma unroll
            for (int i = 0; i < 4; ++i)
#pragma unroll
                for (int j = 0; j < 4; ++j) {
                    mma16816(acc[i][j], ahi[i], bh[j]);
                    mma16816(acc[i][j], alo[i], bh[j]);
                }
        }
    };

    load_stage(0, 0);
    load_stage(1, 1);
#pragma unroll 1
    for (int c = 0; c < 16; ++c) {
        CPA_WAIT1();
        __syncthreads();
        compute(c & 1);
        __syncthreads();
        if (c + 2 < 16) load_stage(c + 2, c & 1);
        else            CPA_COMMIT();
    }

    const int g   = lane >> 2;
    const int tig = lane & 3;

    auto storeC = [&](int m, int col, float v0, float v1) {
        if (MODE == 0) {
            int kl = m >> 4, bb = m & 15;
            int sec = col >> 10, hn = (col >> 6) & 15, d = col & 63;
            if (sec == 0) {
                if (kl >= MLEN) {
                    size_t o = ((size_t)(bb*NH+hn)*QLEN + (kl-MLEN))*DH + d;
                    float b0 = rwb[hn*64 + d], b1 = rwb[hn*64 + d + 1];
                    __half h0, l0, h1, l1;
                    split1h(v0 + b0, h0, l0); split1h(v1 + b1, h1, l1);
                    *(__half2*)&g_Qrwh[o] = __halves2half2(h0, h1);
                    *(__half2*)&g_Qrwl[o] = __halves2half2(l0, l1);
                    float c0 = rrb[hn*64 + d], c1 = rrb[hn*64 + d + 1];
                    split1h(v0 + c0, h0, l0); split1h(v1 + c1, h1, l1);
                    *(__half2*)&g_Qrrh[o] = __halves2half2(h0, h1);
                    *(__half2*)&g_Qrrl[o] = __halves2half2(l0, l1);
                }
            } else if (sec == 1) {
                size_t o = ((size_t)(bb*NH+hn)*KLEN + kl)*DH + d;
                *(__half2*)&g_Khb[o] = __floats2half2_rn(v0, v1);
            } else {
                *(float2*)&g_V[((size_t)(bb*NH+hn)*KLEN + kl)*DH + d] = make_float2(v0, v1);
            }
        } else if (MODE == 1) {
            int hn = col >> 6, d = col & 63;
            *(__half2*)&g_Rkh[((size_t)hn*KLEN + m)*DH + d] = __floats2half2_rn(v0, v1);
        } else {
            *(float2*)&C[(size_t)m * 1024 + col] = make_float2(v0, v1);
        }
    };

#pragma unroll
    for (int i = 0; i < 4; ++i)
#pragma unroll
        for (int j = 0; j < 4; ++j) {
            int m   = m0 + wm*64 + i*16 + g;
            int col = n0 + wn*32 + j*8 + 2*tig;
            storeC(m,     col, acc[i][j][0], acc[i][j][1]);
            storeC(m + 8, col, acc[i][j][2], acc[i][j][3]);
        }
}

// ---------------- BD via HMMA (2 MMAs): BD[i][u] = (q+rrb)·rk ----------------
// smem: Qh 8K | Ql 8K | stage s (2x): Rkh 8K  => 32K
#define BD_SMEM 32768
__global__ __launch_bounds__(128, 2) void bd_mma()
{
    extern __shared__ char sm[];
    const int i0 = blockIdx.x * 64;
    const int bn = blockIdx.y;
    const int nh = bn & 15;
    const int tid = threadIdx.x, wid = tid >> 5, lane = tid & 31;
    const uint32_t smb = smem_u32(sm);

    const int us = (448 - i0) > 0 ? (448 - i0) : 0;
    const int nt = (1024 - us) >> 6;

    const __half* Qh = g_Qrrh + ((size_t)bn*512 + i0) * 64;
    const __half* Ql = g_Qrrl + ((size_t)bn*512 + i0) * 64;

#pragma unroll
    for (int it = 0; it < 4; ++it) {
        int idx = tid + it * 128;
        int r = idx >> 3, ch = idx & 7;
        cpa16(smb + sphys(r, ch),        Qh + r*64 + ch*8);
        cpa16(smb + 8192 + sphys(r, ch), Ql + r*64 + ch*8);
    }
    CPA_COMMIT();

    auto load_rk = [&](int t) {
        if (t < nt) {
            int u0 = us + t * 64;
            uint32_t base = smb + 16384 + (t & 1) * 8192;
#pragma unroll
            for (int it = 0; it < 4; ++it) {
                int idx = tid + it * 128;
                int r = idx >> 3, ch = idx & 7;
                cpa16(base + sphys(r, ch), g_Rkh + ((size_t)nh*1024 + u0 + r)*64 + ch*8);
            }
        }
        CPA_COMMIT();
    };
    load_rk(0);
    load_rk(1);

    uint32_t aqh[4][4], aql[4][4];
    bool afrag = false;

    const int g = lane >> 2, tig = lane & 3;
    const int r0 = i0 + wid * 16 + g;

#pragma unroll 1
    for (int t = 0; t < nt; ++t) {
        CPA_WAIT1();
        __syncthreads();
        if (!afrag) {
            afrag = true;
#pragma unroll
            for (int kc = 0; kc < 4; ++kc) {
                int row = wid * 16 + (lane & 15);
                int ch  = kc * 2 + (lane >> 4);
                ldsm4(aqh[kc], smb + sphys(row, ch));
                ldsm4(aql[kc], smb + 8192 + sphys(row, ch));
            }
        }
        const uint32_t base = smb + 16384 + (t & 1) * 8192;
        const int u0 = us + t * 64;
        __half* bd0 = g_BDh + ((size_t)bn*512 + r0) * 1024 + u0;
        __half* bd1 = bd0 + 8 * 1024;

#pragma unroll
        for (int jt = 0; jt < 8; ++jt) {
            float sa[4] = {0.f, 0.f, 0.f, 0.f};
            uint32_t kh[4][2], tmp[4];
#pragma unroll
            for (int kp = 0; kp < 2; ++kp) {
                int row = jt * 8 + (lane & 7);
                int ch  = kp * 4 + (lane >> 3);
                ldsm4(tmp, base + sphys(row, ch));
                kh[kp*2][0] = tmp[0]; kh[kp*2][1] = tmp[1];
                kh[kp*2+1][0] = tmp[2]; kh[kp*2+1][1] = tmp[3];
            }
#pragma unroll
            for (int kc = 0; kc < 4; ++kc) {
                mma16816(sa, aqh[kc], kh[kc]);
                mma16816(sa, aql[kc], kh[kc]);
            }
            int uc = jt * 8 + 2 * tig;
            *(__half2*)(bd0 + uc) = __floats2half2_rn(sa[0], sa[1]);
            *(__half2*)(bd1 + uc) = __floats2half2_rn(sa[2], sa[3]);
        }
        __syncthreads();
        load_rk(t + 2);
    }
}

// ---------------- fused attention via HMMA + online softmax ----------------
// smem: Qh 8K | Ql 8K | stage s (2x): Kh 8K | Vh 8K  => 48K
#define ATT_SMEM 49152
__global__ __launch_bounds__(128, 2) void attn_mma()
{
    extern __shared__ char sm[];
    const int i0 = blockIdx.x * 64;
    const int bn = blockIdx.y;
    const int b = bn >> 4, nh = bn & 15;
    const int tid = threadIdx.x, wid = tid >> 5, lane = tid & 31;
    const uint32_t smb = smem_u32(sm);

    const int nt = (i0 >> 6) + 9;

    const __half* Qh = g_Qrwh + ((size_t)bn*512 + i0) * 64;
    const __half* Ql = g_Qrwl + ((size_t)bn*512 + i0) * 64;

#pragma unroll
    for (int it = 0; it < 4; ++it) {
        int idx = tid + it * 128;
        int r = idx >> 3, ch = idx & 7;
        cpa16(smb + sphys(r, ch),        Qh + r*64 + ch*8);
        cpa16(smb + 8192 + sphys(r, ch), Ql + r*64 + ch*8);
    }

    auto load_kv = [&](int t) {
        if (t < nt) {
            int j0 = t * 64;
            uint32_t base = smb + 16384 + (t & 1) * 16384;
#pragma unroll
            for (int it = 0; it < 4; ++it) {
                int idx = tid + it * 128;
                int r = idx >> 3, ch = idx & 7;
                cpa16(base + sphys(r, ch),        g_Khb + ((size_t)bn*1024 + j0 + r) * 64 + ch*8);
                cpa16(base + 8192 + sphys(r, ch), g_Vth + ((size_t)bn*64 + r) * 1024 + j0 + ch*8);
            }
        }
        CPA_COMMIT();
    };
    load_kv(0);   // commits Q + KV0 together
    load_kv(1);

    uint32_t aqh[4][4], aql[4][4];
    bool afrag = false;

    const int g = lane >> 2, tig = lane & 3;
    const int r0 = i0 + wid * 16 + g;
    const int r1 = r0 + 8;
    const __half* bd0 = g_BDh + ((size_t)bn*512 + r0) * 1024;
    const __half* bd1 = bd0 + 8 * 1024;

    float mi0 = -1e30f, mi1 = -1e30f, li0 = 0.f, li1 = 0.f;
    float oacc[8][4];
#pragma unroll
    for (int dt = 0; dt < 8; ++dt)
#pragma unroll
        for (int q = 0; q < 4; ++q) oacc[dt][q] = 0.f;

#pragma unroll 1
    for (int t = 0; t < nt; ++t) {
        CPA_WAIT1();
        __syncthreads();
        if (!afrag) {
            afrag = true;
#pragma unroll
            for (int kc = 0; kc < 4; ++kc) {
                int row = wid * 16 + (lane & 15);
                int ch  = kc * 2 + (lane >> 4);
                ldsm4(aqh[kc], smb + sphys(row, ch));
                ldsm4(aql[kc], smb + 8192 + sphys(row, ch));
            }
        }
        const uint32_t kbase = smb + 16384 + (t & 1) * 16384;
        const int j0 = t * 64;

        // ---- S = Q·K^T (2 MMAs) ----
        float sa[8][4];
#pragma unroll
        for (int jt = 0; jt < 8; ++jt) {
            sa[jt][0] = sa[jt][1] = sa[jt][2] = sa[jt][3] = 0.f;
            uint32_t kh[4][2], tmp[4];
#pragma unroll
            for (int kp = 0; kp < 2; ++kp) {
                int row = jt * 8 + (lane & 7);
                int ch  = kp * 4 + (lane >> 3);
                ldsm4(tmp, kbase + sphys(row, ch));
                kh[kp*2][0] = tmp[0]; kh[kp*2][1] = tmp[1];
                kh[kp*2+1][0] = tmp[2]; kh[kp*2+1][1] = tmp[3];
            }
#pragma unroll
            for (int kc = 0; kc < 4; ++kc) {
                mma16816(sa[jt], aqh[kc], kh[kc]);
                mma16816(sa[jt], aql[kc], kh[kc]);
            }
        }

        // ---- + BD, scale, mask ----
#pragma unroll
        for (int jt = 0; jt < 8; ++jt) {
            int j = j0 + jt * 8 + 2 * tig;
            sa[jt][0] = (j     <= r0 + 512) ? (sa[jt][0] + __half2float(bd0[j + 511 - r0])) * 0.125f : -1e30f;
            sa[jt][1] = (j + 1 <= r0 + 512) ? (sa[jt][1] + __half2float(bd0[j + 512 - r0])) * 0.125f : -1e30f;
            sa[jt][2] = (j     <= r1 + 512) ? (sa[jt][2] + __half2float(bd1[j + 511 - r1])) * 0.125f : -1e30f;
            sa[jt][3] = (j + 1 <= r1 + 512) ? (sa[jt][3] + __half2float(bd1[j + 512 - r1])) * 0.125f : -1e30f;
        }

        // ---- online softmax ----
        float m0 = -1e30f, m1 = -1e30f;
#pragma unroll
        for (int jt = 0; jt < 8; ++jt) {
            m0 = fmaxf(m0, fmaxf(sa[jt][0], sa[jt][1]));
            m1 = fmaxf(m1, fmaxf(sa[jt][2], sa[jt][3]));
        }
        m0 = fmaxf(m0, __shfl_xor_sync(0xffffffffu, m0, 1));
        m0 = fmaxf(m0, __shfl_xor_sync(0xffffffffu, m0, 2));
        m1 = fmaxf(m1, __shfl_xor_sync(0xffffffffu, m1, 1));
        m1 = fmaxf(m1, __shfl_xor_sync(0xffffffffu, m1, 2));
        float mn0 = fmaxf(mi0, m0), mn1 = fmaxf(mi1, m1);
        float al0 = __expf(mi0 - mn0), al1 = __expf(mi1 - mn1);
        mi0 = mn0; mi1 = mn1;
        float s0 = 0.f, s1 = 0.f;
#pragma unroll
        for (int jt = 0; jt < 8; ++jt) {
            sa[jt][0] = __expf(sa[jt][0] - mn0); s0 += sa[jt][0];
            sa[jt][1] = __expf(sa[jt][1] - mn0); s0 += sa[jt][1];
            sa[jt][2] = __expf(sa[jt][2] - mn1); s1 += sa[jt][2];
            sa[jt][3] = __expf(sa[jt][3] - mn1); s1 += sa[jt][3];
        }
        s0 += __shfl_xor_sync(0xffffffffu, s0, 1);
        s0 += __shfl_xor_sync(0xffffffffu, s0, 2);
        s1 += __shfl_xor_sync(0xffffffffu, s1, 1);
        s1 += __shfl_xor_sync(0xffffffffu, s1, 2);
        li0 = li0 * al0 + s0;
        li1 = li1 * al1 + s1;
#pragma unroll
        for (int dt = 0; dt < 8; ++dt) {
            oacc[dt][0] *= al0; oacc[dt][1] *= al0;
            oacc[dt][2] *= al1; oacc[dt][3] *= al1;
        }

        // ---- pack P (single fp16) ----
        uint32_t pf[4][4];
#pragma unroll
        for (int kc = 0; kc < 4; ++kc) {
            pf[kc][0] = f2h2(sa[2*kc][0],   sa[2*kc][1]);
            pf[kc][1] = f2h2(sa[2*kc][2],   sa[2*kc][3]);
            pf[kc][2] = f2h2(sa[2*kc+1][0], sa[2*kc+1][1]);
            pf[kc][3] = f2h2(sa[2*kc+1][2], sa[2*kc+1][3]);
        }

        // ---- O += P · V (1 MMA) ----
        const uint32_t vbase = kbase + 8192;
#pragma unroll
        for (int dt = 0; dt < 8; ++dt) {
            uint32_t vh[4][2], tmp[4];
#pragma unroll
            for (int kp = 0; kp < 2; ++kp) {
                int row = dt * 8 + (lane & 7);
                int ch  = kp * 4 + (lane >> 3);
                ldsm4(tmp, vbase + sphys(row, ch));
                vh[kp*2][0] = tmp[0]; vh[kp*2][1] = tmp[1];
                vh[kp*2+1][0] = tmp[2]; vh[kp*2+1][1] = tmp[3];
            }
#pragma unroll
            for (int kc = 0; kc < 4; ++kc)
                mma16816(oacc[dt], pf[kc], vh[kc]);
        }
        __syncthreads();
        load_kv(t + 2);
    }

    // ---- store AV directly as split fp16 ----
    float inv0 = 1.f / li0, inv1 = 1.f / li1;
#pragma unroll
    for (int dt = 0; dt < 8; ++dt) {
        int d = nh * 64 + dt * 8 + 2 * tig;
        size_t o0 = ((size_t)r0 * 16 + b) * 1024 + d;
        size_t o1 = ((size_t)r1 * 16 + b) * 1024 + d;
        __half h0, l0, h1, l1;
        split1h(oacc[dt][0] * inv0, h0, l0); split1h(oacc[dt][1] * inv0, h1, l1);
        *(__half2*)&g_AVh[o0] = __halves2half2(h0, h1);
        *(__half2*)&g_AVl[o0] = __halves2half2(l0, l1);
        split1h(oacc[dt][2] * inv1, h0, l0); split1h(oacc[dt][3] * inv1, h1, l1);
        *(__half2*)&g_AVh[o1] = __halves2half2(h0, h1);
        *(__half2*)&g_AVl[o1] = __halves2half2(l0, l1);
    }
}

// ---------------- residual + layernorm ----------------
__global__ __launch_bounds__(256) void ln_kernel(
    const float* __restrict__ w, const float* __restrict__ gamma,
    const float* __restrict__ beta, float* __restrict__ out)
{
    const int row = blockIdx.x;
    const int tid = threadIdx.x;
    __shared__ float red[256];
    const float* wrow = w   + (size_t)row * 1024;
    float*       orow = out + (size_t)row * 1024;

    float x[4];
    float sum = 0.f;
#pragma unroll
    for (int l = 0; l < 4; l++) {
        int c = tid + l*256;
        x[l] = wrow[c] + orow[c];
        sum += x[l];
    }
    red[tid] = sum; __syncthreads();
    for (int s = 128; s > 0; s >>= 1) {
        if (tid < s) red[tid] += red[tid + s];
        __syncthreads();
    }
    float mu = red[0] * (1.f/1024.f);
    __syncthreads();

    float vs = 0.f;
#pragma unroll
    for (int l = 0; l < 4; l++) { float dx = x[l] - mu; vs += dx*dx; }
    red[tid] = vs; __syncthreads();
    for (int s = 128; s > 0; s >>= 1) {
        if (tid < s) red[tid] += red[tid + s];
        __syncthreads();
    }
    float rstd = rsqrtf(red[0] * (1.f/1024.f) + 1e-6f);

#pragma unroll
    for (int l = 0; l < 4; l++) {
        int c = tid + l*256;
        orow[c] = (x[l] - mu) * rstd * gamma[c] + beta[c];
    }
}

// ---------------- launch ----------------
extern "C" void kernel_launch(void* const* d_in, const int* in_sizes, int n_in,
                              void* d_out, int out_size)
{
    const float* w      = (const float*)d_in[0];
    const float* r      = (const float*)d_in[1];
    const float* mems   = (const float*)d_in[3];
    const float* qkvw   = (const float*)d_in[4];
    const float* rw     = (const float*)d_in[5];
    const float* ow     = (const float*)d_in[6];
    const float* rrb    = (const float*)d_in[7];
    const float* rwbias = (const float*)d_in[8];
    const float* gamma  = (const float*)d_in[9];
    const float* beta   = (const float*)d_in[10];
    float* out = (float*)d_out;

    __half *Ah, *Al, *Wth, *R2h, *R2l, *RWth, *OWth, *AVh, *AVl;
    cudaGetSymbolAddress((void**)&Ah,  g_Ah);  cudaGetSymbolAddress((void**)&Al,  g_Al);
    cudaGetSymbolAddress((void**)&Wth, g_Wth);
    cudaGetSymbolAddress((void**)&R2h, g_R2h); cudaGetSymbolAddress((void**)&R2l, g_R2l);
    cudaGetSymbolAddress((void**)&RWth,g_RWth);
    cudaGetSymbolAddress((void**)&OWth,g_OWth);
    cudaGetSymbolAddress((void**)&AVh, g_AVh); cudaGetSymbolAddress((void**)&AVl, g_AVl);

    cudaFuncSetAttribute(gemm_hf<0>, cudaFuncAttributeMaxDynamicSharedMemorySize, GTC_SMEM);
    cudaFuncSetAttribute(gemm_hf<1>, cudaFuncAttributeMaxDynamicSharedMemorySize, GTC_SMEM);
    cudaFuncSetAttribute(gemm_hf<2>, cudaFuncAttributeMaxDynamicSharedMemorySize, GTC_SMEM);
    cudaFuncSetAttribute(bd_mma,   cudaFuncAttributeMaxDynamicSharedMemorySize, BD_SMEM);
    cudaFuncSetAttribute(attn_mma, cudaFuncAttributeMaxDynamicSharedMemorySize, ATT_SMEM);

    // prep
    split_k <<<8192, 256>>>(mems, Ah, Al, 2097152);
    split_k <<<8192, 256>>>(w, Ah + (size_t)8192*1024, Al + (size_t)8192*1024, 2097152);
    tround_k<<<dim3(96, 32), 256>>>(qkvw, Wth, 1024, 3072);
    split_k <<<1024, 256>>>(r, R2h, R2l, 262144);
    tround_k<<<dim3(32, 32), 256>>>(rw, RWth, 1024, 1024);
    tround_k<<<dim3(32, 32), 256>>>(ow, OWth, 1024, 1024);

    // GEMMs (epilogues write attention operands directly)
    gemm_hf<0><<<dim3(24, 128), 256, GTC_SMEM>>>(Ah, Al, Wth, nullptr, rwbias, rrb);
    gemm_hf<1><<<dim3(8, 8),    256, GTC_SMEM>>>(R2h, R2l, RWth, nullptr, nullptr, nullptr);
    vtrans_k<<<dim3(16, 256), 256>>>();

    // BD + attention
    bd_mma  <<<dim3(8, 256), 128, BD_SMEM>>>();
    attn_mma<<<dim3(8, 256), 128, ATT_SMEM>>>();

    // output projection + layernorm
    gemm_hf<2><<<dim3(8, 64),   256, GTC_SMEM>>>(AVh, AVl, OWth, out, nullptr, nullptr);
    ln_kernel  <<<8192, 256>>>(w, gamma, beta, out);
}

// round 9
// speedup vs baseline: 5.2732x; 1.2449x over previous
#include <cuda_runtime.h>
#include <cuda_fp16.h>
#include <math.h>
#include <stdint.h>

#define QLEN 512
#define MLEN 512
#define KLEN 1024
#define BSZ  16
#define NH   16
#define DH   64
#define DM   1024
#define HID  1024

// ---------------- scratch ----------------
__device__ float  g_V  [(size_t)BSZ*NH*KLEN*DH];          // fp32 V (for transpose)
__device__ __half g_BDh[(size_t)BSZ*NH*QLEN*KLEN];        // BD scores fp16

__device__ __half g_Ah [(size_t)16384*1024];              // cat(mems,w) fp16
__device__ __half g_Wth[(size_t)3072*1024];               // qkv_w^T fp16
__device__ __half g_R2h[(size_t)1024*1024];               // r fp16
__device__ __half g_RWth[(size_t)1024*1024];              // r_w^T fp16
__device__ __half g_OWth[(size_t)1024*1024];              // o_w^T fp16
__device__ __half g_AVh[(size_t)8192*1024];               // attn_vec fp16

__device__ __half g_Qrwh[(size_t)BSZ*NH*QLEN*DH];         // (Q+rw_bias) fp16
__device__ __half g_Qrrh[(size_t)BSZ*NH*QLEN*DH];         // (Q+rr_bias) fp16
__device__ __half g_Khb [(size_t)BSZ*NH*KLEN*DH];         // K fp16
__device__ __half g_Vth [(size_t)BSZ*NH*DH*KLEN];         // V^T fp16
__device__ __half g_Rkh [(size_t)NH*KLEN*DH];             // Rk fp16

// ================= helpers =================
__device__ __forceinline__ uint32_t smem_u32(const void* p) {
    uint32_t a;
    asm("{ .reg .u64 t; cvta.to.shared.u64 t, %1; cvt.u32.u64 %0, t; }" : "=r"(a) : "l"(p));
    return a;
}
__device__ __forceinline__ void ldsm4(uint32_t a[4], uint32_t addr) {
    asm volatile("ldmatrix.sync.aligned.m8n8.x4.shared.b16 {%0,%1,%2,%3}, [%4];"
                 : "=r"(a[0]), "=r"(a[1]), "=r"(a[2]), "=r"(a[3]) : "r"(addr));
}
__device__ __forceinline__ void ldsm2(uint32_t b[2], uint32_t addr) {
    asm volatile("ldmatrix.sync.aligned.m8n8.x2.shared.b16 {%0,%1}, [%2];"
                 : "=r"(b[0]), "=r"(b[1]) : "r"(addr));
}
__device__ __forceinline__ void mma16816(float c[4], const uint32_t a[4], const uint32_t b[2]) {
    asm volatile("mma.sync.aligned.m16n8k16.row.col.f32.f16.f16.f32 "
        "{%0,%1,%2,%3}, {%4,%5,%6,%7}, {%8,%9}, {%0,%1,%2,%3};"
        : "+f"(c[0]), "+f"(c[1]), "+f"(c[2]), "+f"(c[3])
        : "r"(a[0]), "r"(a[1]), "r"(a[2]), "r"(a[3]), "r"(b[0]), "r"(b[1]));
}
__device__ __forceinline__ void cpa16(uint32_t dst, const void* src) {
    asm volatile("cp.async.cg.shared.global [%0], [%1], 16;" :: "r"(dst), "l"(src));
}
#define CPA_COMMIT() asm volatile("cp.async.commit_group;")
#define CPA_WAIT1()  asm volatile("cp.async.wait_group 1;")

__device__ __forceinline__ uint32_t f2h2(float a, float b) {
    __half2 t = __floats2half2_rn(a, b);
    return *reinterpret_cast<uint32_t*>(&t);
}
__device__ __forceinline__ uint32_t sphys(int r, int ch) {   // 128B rows, XOR swizzle
    return (uint32_t)(r * 128 + ((ch ^ (r & 7)) << 4));
}

// ---------------- prep kernels ----------------
__global__ __launch_bounds__(256) void round_k(
    const float* __restrict__ src, __half* __restrict__ h, int n4)
{
    int i = blockIdx.x * 256 + threadIdx.x;
    if (i >= n4) return;
    float4 v = ((const float4*)src)[i];
    __half hh[4];
    hh[0] = __float2half_rn(v.x); hh[1] = __float2half_rn(v.y);
    hh[2] = __float2half_rn(v.z); hh[3] = __float2half_rn(v.w);
    ((uint2*)h)[i] = *(uint2*)hh;
}

// transpose + round: src [K][N] fp32 -> th [N][K] fp16
__global__ __launch_bounds__(256) void tround_k(
    const float* __restrict__ src, __half* __restrict__ th, int K, int N)
{
    __shared__ float tile[32][33];
    const int n0 = blockIdx.x * 32, k0 = blockIdx.y * 32;
    const int tx = threadIdx.x & 31, ty0 = threadIdx.x >> 5;
#pragma unroll
    for (int it = 0; it < 4; ++it) {
        int ty = ty0 + it * 8;
        tile[ty][tx] = src[(size_t)(k0 + ty) * N + n0 + tx];
    }
    __syncthreads();
#pragma unroll
    for (int it = 0; it < 4; ++it) {
        int ty = ty0 + it * 8;
        th[(size_t)(n0 + ty) * K + k0 + tx] = __float2half_rn(tile[tx][ty]);
    }
}

// per-head V transpose: g_V [bn][j][d] fp32 -> g_Vth [bn][d][j] fp16
__global__ __launch_bounds__(256) void vtrans_k()
{
    __shared__ float tile[64][65];
    const int j0 = blockIdx.x * 64;
    const int bn = blockIdx.y;
    const int tid = threadIdx.x;
#pragma unroll
    for (int it = 0; it < 16; ++it) {
        int idx = tid + it * 256;
        int j = idx >> 6, d = idx & 63;
        tile[j][d] = g_V[((size_t)bn * 1024 + j0 + j) * 64 + d];
    }
    __syncthreads();
#pragma unroll
    for (int it = 0; it < 16; ++it) {
        int idx = tid + it * 256;
        int d = idx >> 6, j = idx & 63;
        g_Vth[((size_t)bn * 64 + d) * 1024 + j0 + j] = __float2half_rn(tile[j][d]);
    }
}

// ---------------- fp16 HMMA GEMM (1 MMA), tile 128x128, BK=64 ----------------
// smem/stage 32K: A 16K | B 16K. 2 stages = 64K.
#define GSTG 32768
#define GTC_SMEM (2*GSTG)

template<int MODE>
__global__ __launch_bounds__(256, 1) void gemm_hf(
    const __half* __restrict__ Ah, const __half* __restrict__ Bh,
    float* __restrict__ C, const float* __restrict__ rwb, const float* __restrict__ rrb)
{
    const int m0 = blockIdx.y * 128;
    const int n0 = blockIdx.x * 128;
    if (MODE == 0 && n0 < 1024 && m0 < 8192) return;   // Q of mems: dead

    extern __shared__ char sm[];
    const int tid  = threadIdx.x;
    const int wid  = tid >> 5;
    const int lane = tid & 31;
    const int wm   = wid >> 2;
    const int wn   = wid & 3;
    const uint32_t smb = smem_u32(sm);

    float acc[4][4][4];
#pragma unroll
    for (int i = 0; i < 4; i++)
#pragma unroll
        for (int j = 0; j < 4; j++)
#pragma unroll
            for (int q = 0; q < 4; q++) acc[i][j][q] = 0.f;

    const int lr = tid >> 3;
    const int lc = tid & 7;

    auto load_stage = [&](int c, int stg) {
        const int k0 = c * 64;
        const uint32_t base = smb + stg * GSTG;
#pragma unroll
        for (int it = 0; it < 4; ++it) {
            int r = lr + it * 32;
            uint32_t dst = base + sphys(r, lc);
            cpa16(dst,         Ah + (size_t)(m0 + r) * 1024 + k0 + lc * 8);
            cpa16(dst + 16384, Bh + (size_t)(n0 + r) * 1024 + k0 + lc * 8);
        }
        CPA_COMMIT();
    };

    auto compute = [&](int stg) {
        const uint32_t base = smb + stg * GSTG;
#pragma unroll
        for (int s = 0; s < 4; ++s) {
            uint32_t ah[4][4], bh[4][2];
#pragma unroll
            for (int i = 0; i < 4; ++i) {
                int row = wm * 64 + i * 16 + (lane & 15);
                int ch  = s * 2 + (lane >> 4);
                ldsm4(ah[i], base + sphys(row, ch));
            }
#pragma unroll
            for (int j = 0; j < 4; ++j) {
                int row = wn * 32 + j * 8 + (lane & 7);
                int ch  = s * 2 + ((lane >> 3) & 1);
                ldsm2(bh[j], base + 16384u + sphys(row, ch));
            }
#pragma unroll
            for (int i = 0; i < 4; ++i)
#pragma unroll
                for (int j = 0; j < 4; ++j)
                    mma16816(acc[i][j], ah[i], bh[j]);
        }
    };

    load_stage(0, 0);
    load_stage(1, 1);
#pragma unroll 1
    for (int c = 0; c < 16; ++c) {
        CPA_WAIT1();
        __syncthreads();
        compute(c & 1);
        __syncthreads();
        if (c + 2 < 16) load_stage(c + 2, c & 1);
        else            CPA_COMMIT();
    }

    const int g   = lane >> 2;
    const int tig = lane & 3;

    auto storeC = [&](int m, int col, float v0, float v1) {
        if (MODE == 0) {
            int kl = m >> 4, bb = m & 15;
            int sec = col >> 10, hn = (col >> 6) & 15, d = col & 63;
            if (sec == 0) {
                if (kl >= MLEN) {
                    size_t o = ((size_t)(bb*NH+hn)*QLEN + (kl-MLEN))*DH + d;
                    float b0 = rwb[hn*64 + d], b1 = rwb[hn*64 + d + 1];
                    *(uint32_t*)&g_Qrwh[o] = f2h2(v0 + b0, v1 + b1);
                    float c0 = rrb[hn*64 + d], c1 = rrb[hn*64 + d + 1];
                    *(uint32_t*)&g_Qrrh[o] = f2h2(v0 + c0, v1 + c1);
                }
            } else if (sec == 1) {
                size_t o = ((size_t)(bb*NH+hn)*KLEN + kl)*DH + d;
                *(uint32_t*)&g_Khb[o] = f2h2(v0, v1);
            } else {
                *(float2*)&g_V[((size_t)(bb*NH+hn)*KLEN + kl)*DH + d] = make_float2(v0, v1);
            }
        } else if (MODE == 1) {
            int hn = col >> 6, d = col & 63;
            *(uint32_t*)&g_Rkh[((size_t)hn*KLEN + m)*DH + d] = f2h2(v0, v1);
        } else {
            *(float2*)&C[(size_t)m * 1024 + col] = make_float2(v0, v1);
        }
    };

#pragma unroll
    for (int i = 0; i < 4; ++i)
#pragma unroll
        for (int j = 0; j < 4; ++j) {
            int m   = m0 + wm*64 + i*16 + g;
            int col = n0 + wn*32 + j*8 + 2*tig;
            storeC(m,     col, acc[i][j][0], acc[i][j][1]);
            storeC(m + 8, col, acc[i][j][2], acc[i][j][3]);
        }
}

// ---------------- BD via HMMA (1 MMA): BD[i][u] = (q+rrb)·rk ----------------
// smem: Q 8K | stage s (2x): Rk 8K  => 24K
#define BD_SMEM 24576
__global__ __launch_bounds__(128, 2) void bd_mma()
{
    extern __shared__ char sm[];
    const int i0 = blockIdx.x * 64;
    const int bn = blockIdx.y;
    const int nh = bn & 15;
    const int tid = threadIdx.x, wid = tid >> 5, lane = tid & 31;
    const uint32_t smb = smem_u32(sm);

    const int us = (448 - i0) > 0 ? (448 - i0) : 0;
    const int nt = (1024 - us) >> 6;

    const __half* Qh = g_Qrrh + ((size_t)bn*512 + i0) * 64;

#pragma unroll
    for (int it = 0; it < 4; ++it) {
        int idx = tid + it * 128;
        int r = idx >> 3, ch = idx & 7;
        cpa16(smb + sphys(r, ch), Qh + r*64 + ch*8);
    }
    CPA_COMMIT();

    auto load_rk = [&](int t) {
        if (t < nt) {
            int u0 = us + t * 64;
            uint32_t base = smb + 8192 + (t & 1) * 8192;
#pragma unroll
            for (int it = 0; it < 4; ++it) {
                int idx = tid + it * 128;
                int r = idx >> 3, ch = idx & 7;
                cpa16(base + sphys(r, ch), g_Rkh + ((size_t)nh*1024 + u0 + r)*64 + ch*8);
            }
        }
        CPA_COMMIT();
    };
    load_rk(0);
    load_rk(1);

    uint32_t aq[4][4];
    bool afrag = false;

    const int g = lane >> 2, tig = lane & 3;
    const int r0 = i0 + wid * 16 + g;

#pragma unroll 1
    for (int t = 0; t < nt; ++t) {
        CPA_WAIT1();
        __syncthreads();
        if (!afrag) {
            afrag = true;
#pragma unroll
            for (int kc = 0; kc < 4; ++kc) {
                int row = wid * 16 + (lane & 15);
                int ch  = kc * 2 + (lane >> 4);
                ldsm4(aq[kc], smb + sphys(row, ch));
            }
        }
        const uint32_t base = smb + 8192 + (t & 1) * 8192;
        const int u0 = us + t * 64;
        __half* bd0 = g_BDh + ((size_t)bn*512 + r0) * 1024 + u0;
        __half* bd1 = bd0 + 8 * 1024;

#pragma unroll
        for (int jt = 0; jt < 8; ++jt) {
            float sa[4] = {0.f, 0.f, 0.f, 0.f};
            uint32_t kh[4][2], tmp[4];
#pragma unroll
            for (int kp = 0; kp < 2; ++kp) {
                int row = jt * 8 + (lane & 7);
                int ch  = kp * 4 + (lane >> 3);
                ldsm4(tmp, base + sphys(row, ch));
                kh[kp*2][0] = tmp[0]; kh[kp*2][1] = tmp[1];
                kh[kp*2+1][0] = tmp[2]; kh[kp*2+1][1] = tmp[3];
            }
#pragma unroll
            for (int kc = 0; kc < 4; ++kc)
                mma16816(sa, aq[kc], kh[kc]);
            int uc = jt * 8 + 2 * tig;
            *(__half2*)(bd0 + uc) = __floats2half2_rn(sa[0], sa[1]);
            *(__half2*)(bd1 + uc) = __floats2half2_rn(sa[2], sa[3]);
        }
        __syncthreads();
        load_rk(t + 2);
    }
}

// ---------------- fused attention via HMMA + online softmax ----------------
// smem: Q 8K | stage s (2x): K 8K | V 8K  => 40K
#define ATT_SMEM 40960
__global__ __launch_bounds__(128, 2) void attn_mma()
{
    extern __shared__ char sm[];
    const int i0 = blockIdx.x * 64;
    const int bn = blockIdx.y;
    const int b = bn >> 4, nh = bn & 15;
    const int tid = threadIdx.x, wid = tid >> 5, lane = tid & 31;
    const uint32_t smb = smem_u32(sm);

    const int nt = (i0 >> 6) + 9;

    const __half* Qh = g_Qrwh + ((size_t)bn*512 + i0) * 64;

#pragma unroll
    for (int it = 0; it < 4; ++it) {
        int idx = tid + it * 128;
        int r = idx >> 3, ch = idx & 7;
        cpa16(smb + sphys(r, ch), Qh + r*64 + ch*8);
    }

    auto load_kv = [&](int t) {
        if (t < nt) {
            int j0 = t * 64;
            uint32_t base = smb + 8192 + (t & 1) * 16384;
#pragma unroll
            for (int it = 0; it < 4; ++it) {
                int idx = tid + it * 128;
                int r = idx >> 3, ch = idx & 7;
                cpa16(base + sphys(r, ch),        g_Khb + ((size_t)bn*1024 + j0 + r) * 64 + ch*8);
                cpa16(base + 8192 + sphys(r, ch), g_Vth + ((size_t)bn*64 + r) * 1024 + j0 + ch*8);
            }
        }
        CPA_COMMIT();
    };
    load_kv(0);   // commits Q + KV0 together
    load_kv(1);

    uint32_t aq[4][4];
    bool afrag = false;

    const int g = lane >> 2, tig = lane & 3;
    const int r0 = i0 + wid * 16 + g;
    const int r1 = r0 + 8;
    const __half* bd0 = g_BDh + ((size_t)bn*512 + r0) * 1024;
    const __half* bd1 = bd0 + 8 * 1024;

    float mi0 = -1e30f, mi1 = -1e30f, li0 = 0.f, li1 = 0.f;
    float oacc[8][4];
#pragma unroll
    for (int dt = 0; dt < 8; ++dt)
#pragma unroll
        for (int q = 0; q < 4; ++q) oacc[dt][q] = 0.f;

#pragma unroll 1
    for (int t = 0; t < nt; ++t) {
        CPA_WAIT1();
        __syncthreads();
        if (!afrag) {
            afrag = true;
#pragma unroll
            for (int kc = 0; kc < 4; ++kc) {
                int row = wid * 16 + (lane & 15);
                int ch  = kc * 2 + (lane >> 4);
                ldsm4(aq[kc], smb + sphys(row, ch));
            }
        }
        const uint32_t kbase = smb + 8192 + (t & 1) * 16384;
        const int j0 = t * 64;

        // ---- S = Q·K^T (1 MMA) ----
        float sa[8][4];
#pragma unroll
        for (int jt = 0; jt < 8; ++jt) {
            sa[jt][0] = sa[jt][1] = sa[jt][2] = sa[jt][3] = 0.f;
            uint32_t kh[4][2], tmp[4];
#pragma unroll
            for (int kp = 0; kp < 2; ++kp) {
                int row = jt * 8 + (lane & 7);
                int ch  = kp * 4 + (lane >> 3);
                ldsm4(tmp, kbase + sphys(row, ch));
                kh[kp*2][0] = tmp[0]; kh[kp*2][1] = tmp[1];
                kh[kp*2+1][0] = tmp[2]; kh[kp*2+1][1] = tmp[3];
            }
#pragma unroll
            for (int kc = 0; kc < 4; ++kc)
                mma16816(sa[jt], aq[kc], kh[kc]);
        }

        // ---- + BD, scale, mask ----
#pragma unroll
        for (int jt = 0; jt < 8; ++jt) {
            int j = j0 + jt * 8 + 2 * tig;
            sa[jt][0] = (j     <= r0 + 512) ? (sa[jt][0] + __half2float(bd0[j + 511 - r0])) * 0.125f : -1e30f;
            sa[jt][1] = (j + 1 <= r0 + 512) ? (sa[jt][1] + __half2float(bd0[j + 512 - r0])) * 0.125f : -1e30f;
            sa[jt][2] = (j     <= r1 + 512) ? (sa[jt][2] + __half2float(bd1[j + 511 - r1])) * 0.125f : -1e30f;
            sa[jt][3] = (j + 1 <= r1 + 512) ? (sa[jt][3] + __half2float(bd1[j + 512 - r1])) * 0.125f : -1e30f;
        }

        // ---- online softmax ----
        float m0 = -1e30f, m1 = -1e30f;
#pragma unroll
        for (int jt = 0; jt < 8; ++jt) {
            m0 = fmaxf(m0, fmaxf(sa[jt][0], sa[jt][1]));
            m1 = fmaxf(m1, fmaxf(sa[jt][2], sa[jt][3]));
        }
        m0 = fmaxf(m0, __shfl_xor_sync(0xffffffffu, m0, 1));
        m0 = fmaxf(m0, __shfl_xor_sync(0xffffffffu, m0, 2));
        m1 = fmaxf(m1, __shfl_xor_sync(0xffffffffu, m1, 1));
        m1 = fmaxf(m1, __shfl_xor_sync(0xffffffffu, m1, 2));
        float mn0 = fmaxf(mi0, m0), mn1 = fmaxf(mi1, m1);
        float al0 = __expf(mi0 - mn0), al1 = __expf(mi1 - mn1);
        mi0 = mn0; mi1 = mn1;
        float s0 = 0.f, s1 = 0.f;
#pragma unroll
        for (int jt = 0; jt < 8; ++jt) {
            sa[jt][0] = __expf(sa[jt][0] - mn0); s0 += sa[jt][0];
            sa[jt][1] = __expf(sa[jt][1] - mn0); s0 += sa[jt][1];
            sa[jt][2] = __expf(sa[jt][2] - mn1); s1 += sa[jt][2];
            sa[jt][3] = __expf(sa[jt][3] - mn1); s1 += sa[jt][3];
        }
        s0 += __shfl_xor_sync(0xffffffffu, s0, 1);
        s0 += __shfl_xor_sync(0xffffffffu, s0, 2);
        s1 += __shfl_xor_sync(0xffffffffu, s1, 1);
        s1 += __shfl_xor_sync(0xffffffffu, s1, 2);
        li0 = li0 * al0 + s0;
        li1 = li1 * al1 + s1;
#pragma unroll
        for (int dt = 0; dt < 8; ++dt) {
            oacc[dt][0] *= al0; oacc[dt][1] *= al0;
            oacc[dt][2] *= al1; oacc[dt][3] *= al1;
        }

        // ---- pack P (fp16) ----
        uint32_t pf[4][4];
#pragma unroll
        for (int kc = 0; kc < 4; ++kc) {
            pf[kc][0] = f2h2(sa[2*kc][0],   sa[2*kc][1]);
            pf[kc][1] = f2h2(sa[2*kc][2],   sa[2*kc][3]);
            pf[kc][2] = f2h2(sa[2*kc+1][0], sa[2*kc+1][1]);
            pf[kc][3] = f2h2(sa[2*kc+1][2], sa[2*kc+1][3]);
        }

        // ---- O += P · V (1 MMA) ----
        const uint32_t vbase = kbase + 8192;
#pragma unroll
        for (int dt = 0; dt < 8; ++dt) {
            uint32_t vh[4][2], tmp[4];
#pragma unroll
            for (int kp = 0; kp < 2; ++kp) {
                int row = dt * 8 + (lane & 7);
                int ch  = kp * 4 + (lane >> 3);
                ldsm4(tmp, vbase + sphys(row, ch));
                vh[kp*2][0] = tmp[0]; vh[kp*2][1] = tmp[1];
                vh[kp*2+1][0] = tmp[2]; vh[kp*2+1][1] = tmp[3];
            }
#pragma unroll
            for (int kc = 0; kc < 4; ++kc)
                mma16816(oacc[dt], pf[kc], vh[kc]);
        }
        __syncthreads();
        load_kv(t + 2);
    }

    // ---- store AV as fp16 ----
    float inv0 = 1.f / li0, inv1 = 1.f / li1;
#pragma unroll
    for (int dt = 0; dt < 8; ++dt) {
        int d = nh * 64 + dt * 8 + 2 * tig;
        *(uint32_t*)&g_AVh[((size_t)r0 * 16 + b) * 1024 + d] =
            f2h2(oacc[dt][0] * inv0, oacc[dt][1] * inv0);
        *(uint32_t*)&g_AVh[((size_t)r1 * 16 + b) * 1024 + d] =
            f2h2(oacc[dt][2] * inv1, oacc[dt][3] * inv1);
    }
}

// ---------------- residual + layernorm (warp-shuffle reductions) ----------------
__global__ __launch_bounds__(256) void ln_kernel(
    const float* __restrict__ w, const float* __restrict__ gamma,
    const float* __restrict__ beta, float* __restrict__ out)
{
    const int row = blockIdx.x;
    const int tid = threadIdx.x;
    const int lane = tid & 31, wid = tid >> 5;
    __shared__ float wred[8];
    const float* wrow = w   + (size_t)row * 1024;
    float*       orow = out + (size_t)row * 1024;

    float x[4];
    float sum = 0.f;
#pragma unroll
    for (int l = 0; l < 4; l++) {
        int c = tid + l*256;
        x[l] = wrow[c] + orow[c];
        sum += x[l];
    }
#pragma unroll
    for (int off = 16; off; off >>= 1) sum += __shfl_xor_sync(0xffffffffu, sum, off);
    if (lane == 0) wred[wid] = sum;
    __syncthreads();
    float tot = 0.f;
#pragma unroll
    for (int q = 0; q < 8; ++q) tot += wred[q];
    float mu = tot * (1.f/1024.f);
    __syncthreads();

    float vs = 0.f;
#pragma unroll
    for (int l = 0; l < 4; l++) { float dx = x[l] - mu; vs += dx*dx; }
#pragma unroll
    for (int off = 16; off; off >>= 1) vs += __shfl_xor_sync(0xffffffffu, vs, off);
    if (lane == 0) wred[wid] = vs;
    __syncthreads();
    float vtot = 0.f;
#pragma unroll
    for (int q = 0; q < 8; ++q) vtot += wred[q];
    float rstd = rsqrtf(vtot * (1.f/1024.f) + 1e-6f);

#pragma unroll
    for (int l = 0; l < 4; l++) {
        int c = tid + l*256;
        orow[c] = (x[l] - mu) * rstd * gamma[c] + beta[c];
    }
}

// ---------------- launch ----------------
extern "C" void kernel_launch(void* const* d_in, const int* in_sizes, int n_in,
                              void* d_out, int out_size)
{
    const float* w      = (const float*)d_in[0];
    const float* r      = (const float*)d_in[1];
    const float* mems   = (const float*)d_in[3];
    const float* qkvw   = (const float*)d_in[4];
    const float* rw     = (const float*)d_in[5];
    const float* ow     = (const float*)d_in[6];
    const float* rrb    = (const float*)d_in[7];
    const float* rwbias = (const float*)d_in[8];
    const float* gamma  = (const float*)d_in[9];
    const float* beta   = (const float*)d_in[10];
    float* out = (float*)d_out;

    __half *Ah, *Wth, *R2h, *RWth, *OWth, *AVh;
    cudaGetSymbolAddress((void**)&Ah,  g_Ah);
    cudaGetSymbolAddress((void**)&Wth, g_Wth);
    cudaGetSymbolAddress((void**)&R2h, g_R2h);
    cudaGetSymbolAddress((void**)&RWth,g_RWth);
    cudaGetSymbolAddress((void**)&OWth,g_OWth);
    cudaGetSymbolAddress((void**)&AVh, g_AVh);

    cudaFuncSetAttribute(gemm_hf<0>, cudaFuncAttributeMaxDynamicSharedMemorySize, GTC_SMEM);
    cudaFuncSetAttribute(gemm_hf<1>, cudaFuncAttributeMaxDynamicSharedMemorySize, GTC_SMEM);
    cudaFuncSetAttribute(gemm_hf<2>, cudaFuncAttributeMaxDynamicSharedMemorySize, GTC_SMEM);
    cudaFuncSetAttribute(bd_mma,   cudaFuncAttributeMaxDynamicSharedMemorySize, BD_SMEM);
    cudaFuncSetAttribute(attn_mma, cudaFuncAttributeMaxDynamicSharedMemorySize, ATT_SMEM);

    // prep
    round_k <<<8192, 256>>>(mems, Ah, 2097152);
    round_k <<<8192, 256>>>(w, Ah + (size_t)8192*1024, 2097152);
    tround_k<<<dim3(96, 32), 256>>>(qkvw, Wth, 1024, 3072);
    round_k <<<1024, 256>>>(r, R2h, 262144);
    tround_k<<<dim3(32, 32), 256>>>(rw, RWth, 1024, 1024);
    tround_k<<<dim3(32, 32), 256>>>(ow, OWth, 1024, 1024);

    // GEMMs (epilogues write attention operands directly)
    gemm_hf<0><<<dim3(24, 128), 256, GTC_SMEM>>>(Ah, Wth, nullptr, rwbias, rrb);
    gemm_hf<1><<<dim3(8, 8),    256, GTC_SMEM>>>(R2h, RWth, nullptr, nullptr, nullptr);
    vtrans_k<<<dim3(16, 256), 256>>>();

    // BD + attention
    bd_mma  <<<dim3(8, 256), 128, BD_SMEM>>>();
    attn_mma<<<dim3(8, 256), 128, ATT_SMEM>>>();

    // output projection + layernorm
    gemm_hf<2><<<dim3(8, 64),   256, GTC_SMEM>>>(AVh, OWth, out, nullptr, nullptr);
    ln_kernel  <<<8192, 256>>>(w, gamma, beta, out);
}